// round 9
// baseline (speedup 1.0000x reference)
#include <cuda_runtime.h>
#include <cuda_bf16.h>
#include <cstdint>
#include <cstddef>

#define NN 50000
#define NE 600000
#define DD 128
#define HH 256
#define TM 128

// ============================ device scratch ================================
__device__ float g_agg[(size_t)NN * DD];
__device__ float g_PQ[(size_t)NN * 512];    // per-node [P|Q]: P=feat@W0a+b0, Q=feat@W0b
// weights transposed to [N][K] row-major, bf16 hi/lo split
__device__ __nv_bfloat16 g_c0h[512 * DD],  g_c0l[512 * DD];   // msg [W0a|W0b]^T : [512][128]
__device__ __nv_bfloat16 g_mW1h[DD * HH],  g_mW1l[DD * HH];   // msg W1^T: [128][256]
__device__ __nv_bfloat16 g_uW0h[HH * HH],  g_uW0l[HH * HH];   // upd W0^T: [256][256]
__device__ __nv_bfloat16 g_uW1h[DD * HH],  g_uW1l[DD * HH];   // upd W1^T: [128][256]

// ============================ PTX helpers ===================================
__device__ __forceinline__ uint32_t smem_u32(const void* p) {
    uint32_t a;
    asm("{ .reg .u64 t; cvta.to.shared.u64 t, %1; cvt.u32.u64 %0, t; }" : "=r"(a) : "l"(p));
    return a;
}
__device__ __forceinline__ void ldsm_x4(uint32_t& r0, uint32_t& r1, uint32_t& r2,
                                        uint32_t& r3, uint32_t addr) {
    asm volatile("ldmatrix.sync.aligned.m8n8.x4.shared.b16 {%0,%1,%2,%3}, [%4];"
                 : "=r"(r0), "=r"(r1), "=r"(r2), "=r"(r3) : "r"(addr));
}
__device__ __forceinline__ void mma_bf16(float* d, const uint32_t* a,
                                         uint32_t b0, uint32_t b1) {
    asm volatile(
        "mma.sync.aligned.m16n8k16.row.col.f32.bf16.bf16.f32 "
        "{%0,%1,%2,%3},{%4,%5,%6,%7},{%8,%9},{%0,%1,%2,%3};"
        : "+f"(d[0]), "+f"(d[1]), "+f"(d[2]), "+f"(d[3])
        : "r"(a[0]), "r"(a[1]), "r"(a[2]), "r"(a[3]), "r"(b0), "r"(b1));
}
__device__ __forceinline__ uint32_t pack_bf16(float a, float b) {
    __nv_bfloat162 t = __floats2bfloat162_rn(a, b);
    return *reinterpret_cast<uint32_t*>(&t);
}
__device__ __forceinline__ void cpa16(uint32_t dst, const void* src) {
    asm volatile("cp.async.cg.shared.global [%0], [%1], 16;"
                 :: "r"(dst), "l"(src) : "memory");
}
#define CP_COMMIT() asm volatile("cp.async.commit_group;" ::: "memory")
#define CP_WAIT(n)  asm volatile("cp.async.wait_group %0;" :: "n"(n) : "memory")
#define NB_SYNC(id)   asm volatile("bar.sync %0, 512;"   :: "n"(id) : "memory")
#define NB_ARRIVE(id) asm volatile("bar.arrive %0, 512;" :: "n"(id) : "memory")
#define MEMBAR_CTA()  asm volatile("membar.cta;" ::: "memory")

// store float4 -> hi/lo bf16x2 pairs at byte offset off in two tiles
__device__ __forceinline__ void split_store(char* smc, int hi_base, int lo_base,
                                            int off, float4 v) {
    __nv_bfloat16 h0 = __float2bfloat16(v.x), h1 = __float2bfloat16(v.y);
    __nv_bfloat16 h2 = __float2bfloat16(v.z), h3 = __float2bfloat16(v.w);
    uint2 H, L;
    H.x = pack_bf16(v.x, v.y);
    H.y = pack_bf16(v.z, v.w);
    L.x = pack_bf16(v.x - __bfloat162float(h0), v.y - __bfloat162float(h1));
    L.y = pack_bf16(v.z - __bfloat162float(h2), v.w - __bfloat162float(h3));
    *reinterpret_cast<uint2*>(smc + hi_base + off) = H;
    *reinterpret_cast<uint2*>(smc + lo_base + off) = L;
}

__device__ __forceinline__ float4 relu_add4(float4 p, float4 q) {
    float4 v;
    v.x = fmaxf(p.x + q.x, 0.f);
    v.y = fmaxf(p.y + q.y, 0.f);
    v.z = fmaxf(p.z + q.z, 0.f);
    v.w = fmaxf(p.w + q.w, 0.f);
    return v;
}

// =========================== prelude kernels ================================
__global__ void zero_agg_kernel() {
    const size_t n4 = (size_t)NN * DD / 4;
    float4 z = make_float4(0.f, 0.f, 0.f, 0.f);
    for (size_t i = (size_t)blockIdx.x * blockDim.x + threadIdx.x; i < n4;
         i += (size_t)gridDim.x * blockDim.x)
        reinterpret_cast<float4*>(g_agg)[i] = z;
}

__device__ __forceinline__ void put_split(__nv_bfloat16* h, __nv_bfloat16* l,
                                          int idx, float w) {
    __nv_bfloat16 hi = __float2bfloat16(w);
    h[idx] = hi;
    l[idx] = __float2bfloat16(w - __bfloat162float(hi));
}

__global__ void conv_w_kernel(const float* __restrict__ mW0, const float* __restrict__ uW0,
                              const float* __restrict__ mW1, const float* __restrict__ uW1) {
    int i = blockIdx.x * blockDim.x + threadIdx.x;
    if (i >= 196608) return;
    if (i < 65536) {
        int n = i >> 7, k = i & 127;
        float w = (n < 256) ? mW0[k * HH + n] : mW0[(128 + k) * HH + (n - 256)];
        put_split(g_c0h, g_c0l, n * DD + k, w);
    } else if (i < 131072) {
        int j = i - 65536, k = j >> 8, n = j & 255;
        put_split(g_uW0h, g_uW0l, n * HH + k, uW0[j]);
    } else if (i < 163840) {
        int j = i - 131072, k = j >> 7, n = j & 127;
        put_split(g_mW1h, g_mW1l, n * HH + k, mW1[j]);
    } else {
        int j = i - 163840, k = j >> 7, n = j & 127;
        put_split(g_uW1h, g_uW1l, n * HH + k, uW1[j]);
    }
}

// generic B-chunk stager: nrows x 32 K-cols, BROW=80, 512 threads
__device__ __forceinline__ void stage_b(uint32_t bbase, int tid,
                                        const __nv_bfloat16* Wh,
                                        const __nv_bfloat16* Wl,
                                        int row_base, int chunk, int nrows,
                                        int kstride, int bhalf) {
    #pragma unroll
    for (int i = 0; i < 2; ++i) {
        int idx = tid + i * 512;
        if (idx < nrows * 4) {
            int row = idx >> 2, seg = idx & 3;
            uint32_t d = bbase + (uint32_t)(row * 80 + seg * 16);
            const int so = (row_base + row) * kstride + chunk * 32 + seg * 8;
            cpa16(d, Wh + so);
            cpa16(d + bhalf, Wl + so);
        }
    }
}

// ======================= PQ precompute kernel ===============================
#define P_B0   0
#define P_AHI  4096
#define P_ALO  (4096 + 34816)           // 38912
#define P_B    (38912 + 34816)          // 73728
#define P_BHALF 20480
#define P_BBUF  40960
#define P_SMEM  (73728 + 2 * P_BBUF)    // 155648
#define AROW2  272

__global__ void __launch_bounds__(512, 1) pq_kernel(const float* __restrict__ feat,
                                                    const float* __restrict__ b0) {
    extern __shared__ char smc[];
    const uint32_t sb = smem_u32(smc);
    const int tid  = threadIdx.x;
    const int wid  = tid >> 5;
    const int lane = tid & 31;
    const int wr   = wid & 3;
    const int wc   = wid >> 2;
    const int lrow = ((lane >> 3) & 1) * 8 + (lane & 7);
    const int lcol = (lane >> 4) * 8;
    float* b0s = reinterpret_cast<float*>(smc + P_B0);

    const int tile0 = blockIdx.x * TM;
    if (tid < 256) b0s[tid] = b0[tid];

    stage_b(sb + P_B, tid, g_c0h, g_c0l, 0, 0, 256, DD, P_BHALF);
    CP_COMMIT();

    {
        const float4* f4 = reinterpret_cast<const float4*>(feat);
        #pragma unroll
        for (int it = 0; it < 8; ++it) {
            int ci = tid + it * 512;
            int r  = ci >> 5;
            int c4 = ci & 31;
            int node = tile0 + r;
            float4 v = make_float4(0.f, 0.f, 0.f, 0.f);
            if (node < NN) v = f4[(size_t)node * 32 + c4];
            split_store(smc, P_AHI, P_ALO, r * AROW2 + c4 * 8, v);
        }
    }
    __syncthreads();

    for (int h = 0; h < 2; ++h) {
        float acc[2][8][4];
        #pragma unroll
        for (int m = 0; m < 2; ++m)
            #pragma unroll
            for (int n = 0; n < 8; ++n)
                #pragma unroll
                for (int q = 0; q < 4; ++q) acc[m][n][q] = 0.f;

        for (int c = 0; c < 4; ++c) {
            int g = h * 4 + c;
            if (g < 7)
                stage_b(sb + P_B + (uint32_t)((g + 1) & 1) * P_BBUF, tid,
                        g_c0h, g_c0l, ((g + 1) >> 2) * 256, (g + 1) & 3, 256, DD, P_BHALF);
            CP_COMMIT();
            CP_WAIT(1);
            __syncthreads();
            const uint32_t bbase = sb + P_B + (uint32_t)(g & 1) * P_BBUF;
            #pragma unroll
            for (int ks = 0; ks < 2; ++ks) {
                const int kA = c * 32 + ks * 16;
                uint32_t ah[2][4], al[2][4];
                #pragma unroll
                for (int mt = 0; mt < 2; ++mt) {
                    uint32_t aaddr = sb + P_AHI +
                        (uint32_t)((wr * 32 + mt * 16 + lrow) * AROW2 + (kA + lcol) * 2);
                    ldsm_x4(ah[mt][0], ah[mt][1], ah[mt][2], ah[mt][3], aaddr);
                    ldsm_x4(al[mt][0], al[mt][1], al[mt][2], al[mt][3],
                            aaddr + (P_ALO - P_AHI));
                }
                #pragma unroll
                for (int np = 0; np < 4; ++np) {
                    uint32_t baddr = bbase +
                        (uint32_t)((wc * 64 + np * 16 + lrow) * 80 + (ks * 16 + lcol) * 2);
                    uint32_t bh0, bh1, bh2, bh3, bl0, bl1, bl2, bl3;
                    ldsm_x4(bh0, bh1, bh2, bh3, baddr);
                    ldsm_x4(bl0, bl1, bl2, bl3, baddr + P_BHALF);
                    const int nb = np * 2;
                    #pragma unroll
                    for (int mt = 0; mt < 2; ++mt) {
                        mma_bf16(acc[mt][nb],     ah[mt], bh0, bh2);
                        mma_bf16(acc[mt][nb + 1], ah[mt], bh1, bh3);
                        mma_bf16(acc[mt][nb],     al[mt], bh0, bh2);
                        mma_bf16(acc[mt][nb + 1], al[mt], bh1, bh3);
                        mma_bf16(acc[mt][nb],     ah[mt], bl0, bl2);
                        mma_bf16(acc[mt][nb + 1], ah[mt], bl1, bl3);
                    }
                }
            }
            __syncthreads();
        }

        #pragma unroll
        for (int mt = 0; mt < 2; ++mt)
            #pragma unroll
            for (int nt = 0; nt < 8; ++nt) {
                int cc = wc * 64 + nt * 8 + 2 * (lane & 3);
                int r0 = wr * 32 + mt * 16 + (lane >> 2);
                int r1 = r0 + 8;
                float* d = acc[mt][nt];
                float bb0 = (h == 0) ? b0s[cc] : 0.f;
                float bb1 = (h == 0) ? b0s[cc + 1] : 0.f;
                int n0 = tile0 + r0, n1 = tile0 + r1;
                if (n0 < NN)
                    *reinterpret_cast<float2*>(g_PQ + (size_t)n0 * 512 + h * 256 + cc) =
                        make_float2(d[0] + bb0, d[1] + bb1);
                if (n1 < NN)
                    *reinterpret_cast<float2*>(g_PQ + (size_t)n1 * 512 + h * 256 + cc) =
                        make_float2(d[2] + bb0, d[3] + bb1);
            }
    }
}

// ================= edge kernel (persistent, warp-specialized) ===============
// producers (warps 8-15): H chunks = relu(P[from]+Q[to]) -> bf16 hi/lo A bufs
// consumers (warps 0-7):  GEMM2 MMA + atomic scatter epilogue
// handshake: named barriers FULL0=1, FULL1=2, EMPTY0=3, EMPTY1=4 (count 512)
#define E_B1   0                       // 128 floats
#define E_TO0  512                     // 128 ints (tile parity 0)
#define E_TO1  1024                    // 128 ints (tile parity 1)
#define E_A    4096                    // 2 A buffers: each hi 10240 + lo 10240
#define E_B    (4096 + 40960)          // 45056; B hi: 8 chunks * 10240; lo at +81920
#define E_SMEM (45056 + 163840)        // 208896

#define EDGE_TILES ((NE + TM - 1) / TM)

__global__ void __launch_bounds__(512, 1) edge_kernel(
    const int* __restrict__ from_idx, const int* __restrict__ to_idx,
    const float* __restrict__ b1)
{
    extern __shared__ char smc[];
    const uint32_t sb = smem_u32(smc);
    const int tid  = threadIdx.x;
    const int wid  = tid >> 5;
    const int lane = tid & 31;

    float* b1s = reinterpret_cast<float*>(smc + E_B1);
    if (tid < 128) b1s[tid] = b1[tid];

    // ---- stage resident W1 hi/lo once (all threads) ----
    #pragma unroll
    for (int i = 0; i < 8; ++i) {
        int idx = tid + i * 512;          // c*512 + row*4 + seg
        int c = idx >> 9, rs = idx & 511;
        int row = rs >> 2, seg = rs & 3;
        uint32_t d = sb + E_B + (uint32_t)(c * 10240 + row * 80 + seg * 16);
        int so = row * HH + c * 32 + seg * 8;
        cpa16(d, g_mW1h + so);
        cpa16(d + 81920, g_mW1l + so);
    }
    CP_COMMIT();
    CP_WAIT(0);
    __syncthreads();

    const float4* pq4 = reinterpret_cast<const float4*>(g_PQ);

    if (wid < 8) {
        // ============================ CONSUMERS =============================
        const int wr   = wid & 3;
        const int wc   = wid >> 2;           // 0..1, 64 cols each
        const int lrow = ((lane >> 3) & 1) * 8 + (lane & 7);
        const int lcol = (lane >> 4) * 8;

        NB_ARRIVE(3);                        // prime empty0
        NB_ARRIVE(4);                        // prime empty1

        int tcnt = 0;
        for (int tile = blockIdx.x; tile < EDGE_TILES; tile += gridDim.x, ++tcnt) {
            const int tile0 = tile * TM;
            const int rem   = min(TM, NE - tile0);

            float acc[2][8][4];
            #pragma unroll
            for (int m = 0; m < 2; ++m)
                #pragma unroll
                for (int n = 0; n < 8; ++n)
                    #pragma unroll
                    for (int q = 0; q < 4; ++q) acc[m][n][q] = 0.f;

            #pragma unroll
            for (int c = 0; c < 8; ++c) {
                if (c & 1) { NB_SYNC(2); } else { NB_SYNC(1); }
                const uint32_t abase = sb + E_A + (uint32_t)((c & 1) * 20480);
                const uint32_t bbase = sb + E_B + (uint32_t)(c * 10240);
                #pragma unroll
                for (int ks = 0; ks < 2; ++ks) {
                    uint32_t ah[2][4], al[2][4];
                    #pragma unroll
                    for (int mt = 0; mt < 2; ++mt) {
                        uint32_t aaddr = abase +
                            (uint32_t)((wr * 32 + mt * 16 + lrow) * 80 +
                                       (ks * 16 + lcol) * 2);
                        ldsm_x4(ah[mt][0], ah[mt][1], ah[mt][2], ah[mt][3], aaddr);
                        ldsm_x4(al[mt][0], al[mt][1], al[mt][2], al[mt][3],
                                aaddr + 10240);
                    }
                    #pragma unroll
                    for (int np = 0; np < 4; ++np) {
                        uint32_t baddr = bbase +
                            (uint32_t)((wc * 64 + np * 16 + lrow) * 80 +
                                       (ks * 16 + lcol) * 2);
                        uint32_t bh0, bh1, bh2, bh3, bl0, bl1, bl2, bl3;
                        ldsm_x4(bh0, bh1, bh2, bh3, baddr);
                        ldsm_x4(bl0, bl1, bl2, bl3, baddr + 81920);
                        const int nb = np * 2;
                        #pragma unroll
                        for (int mt = 0; mt < 2; ++mt) {
                            mma_bf16(acc[mt][nb],     ah[mt], bh0, bh2);
                            mma_bf16(acc[mt][nb + 1], ah[mt], bh1, bh3);
                            mma_bf16(acc[mt][nb],     al[mt], bh0, bh2);
                            mma_bf16(acc[mt][nb + 1], al[mt], bh1, bh3);
                            mma_bf16(acc[mt][nb],     ah[mt], bl0, bl2);
                            mma_bf16(acc[mt][nb + 1], ah[mt], bl1, bl3);
                        }
                    }
                }
                if (c & 1) { NB_ARRIVE(4); } else { NB_ARRIVE(3); }
            }

            // ---- epilogue: bias+relu, scatter-atomic ----
            const int* stob =
                reinterpret_cast<const int*>(smc + E_TO0 + (tcnt & 1) * 512);
            #pragma unroll
            for (int mt = 0; mt < 2; ++mt)
                #pragma unroll
                for (int nt = 0; nt < 8; ++nt) {
                    int cc = wc * 64 + nt * 8 + 2 * (lane & 3);
                    int r0 = wr * 32 + mt * 16 + (lane >> 2);
                    int r1 = r0 + 8;
                    float* d = acc[mt][nt];
                    float v0 = fmaxf(d[0] + b1s[cc], 0.f);
                    float v1 = fmaxf(d[1] + b1s[cc + 1], 0.f);
                    float v2 = fmaxf(d[2] + b1s[cc], 0.f);
                    float v3 = fmaxf(d[3] + b1s[cc + 1], 0.f);
                    if (r0 < rem) {
                        float* a = g_agg + (size_t)stob[r0] * DD + cc;
                        atomicAdd(a, v0);
                        atomicAdd(a + 1, v1);
                    }
                    if (r1 < rem) {
                        float* a = g_agg + (size_t)stob[r1] * DD + cc;
                        atomicAdd(a, v2);
                        atomicAdd(a + 1, v3);
                    }
                }
        }
    } else {
        // ============================ PRODUCERS =============================
        const int ptid = tid - 256;          // 0..255
        const int ra   = ptid >> 2;          // 0..63
        const int rb   = ra + 64;
        const int sg   = ptid & 3;

        int tcnt = 0;
        for (int tile = blockIdx.x; tile < EDGE_TILES; tile += gridDim.x, ++tcnt) {
            const int tile0 = tile * TM;
            const int rem   = min(TM, NE - tile0);

            int fa = (ra < rem) ? from_idx[tile0 + ra] : 0;
            int ta = (ra < rem) ? to_idx[tile0 + ra]   : 0;
            int fb = (rb < rem) ? from_idx[tile0 + rb] : 0;
            int tb = (rb < rem) ? to_idx[tile0 + rb]   : 0;

            int* stob = reinterpret_cast<int*>(smc + E_TO0 + (tcnt & 1) * 512);
            if (sg == 0) { stob[ra] = ta; stob[rb] = tb; }

            const size_t pa = (size_t)fa * 128 + sg * 2;
            const size_t qa = (size_t)ta * 128 + 64 + sg * 2;
            const size_t pb = (size_t)fb * 128 + sg * 2;
            const size_t qb = (size_t)tb * 128 + 64 + sg * 2;
            const int offa = ra * 80 + sg * 16;
            const int offb = rb * 80 + sg * 16;

            #pragma unroll
            for (int c = 0; c < 8; ++c) {
                // issue gathers BEFORE the empty-wait (latency overlaps wait)
                float4 pa0 = pq4[pa + c * 8], pa1 = pq4[pa + c * 8 + 1];
                float4 qa0 = pq4[qa + c * 8], qa1 = pq4[qa + c * 8 + 1];
                float4 pb0 = pq4[pb + c * 8], pb1 = pq4[pb + c * 8 + 1];
                float4 qb0 = pq4[qb + c * 8], qb1 = pq4[qb + c * 8 + 1];

                if (c & 1) { NB_SYNC(4); } else { NB_SYNC(3); }
                const int ab = E_A + (c & 1) * 20480;
                split_store(smc, ab, ab + 10240, offa,     relu_add4(pa0, qa0));
                split_store(smc, ab, ab + 10240, offa + 8, relu_add4(pa1, qa1));
                split_store(smc, ab, ab + 10240, offb,     relu_add4(pb0, qb0));
                split_store(smc, ab, ab + 10240, offb + 8, relu_add4(pb1, qb1));
                MEMBAR_CTA();
                if (c & 1) { NB_ARRIVE(2); } else { NB_ARRIVE(1); }
            }
        }
    }
}

// ============================ node kernel ===================================
#define SM_B0   0
#define SM_B1   1024
#define SM_AHI  4096
#define SM_ALO  (4096 + 67584)          // 71680
#define SM_B    (71680 + 67584)         // 139264
#define N_BHALF 20480
#define N_BBUF  40960
#define N_SMEM  (139264 + 2 * N_BBUF)   // 221184
#define AROW 528

__global__ void __launch_bounds__(512, 1) node_kernel(
    const float* __restrict__ feat,
    const float* __restrict__ b0, const float* __restrict__ b1,
    float* __restrict__ outp)
{
    extern __shared__ char smc[];
    const uint32_t sb = smem_u32(smc);
    const int tid  = threadIdx.x;
    const int wid  = tid >> 5;
    const int lane = tid & 31;
    const int wr   = wid & 3;
    const int wc   = wid >> 2;
    const int lrow = ((lane >> 3) & 1) * 8 + (lane & 7);
    const int lcol = (lane >> 4) * 8;

    float* b0s = reinterpret_cast<float*>(smc + SM_B0);
    float* b1s = reinterpret_cast<float*>(smc + SM_B1);

    const int tile0 = blockIdx.x * TM;

    if (tid < 256) b0s[tid] = b0[tid];
    if (tid >= 256 && tid < 384) b1s[tid - 256] = b1[tid - 256];

    stage_b(sb + SM_B, tid, g_uW0h, g_uW0l, 0, 0, 256, HH, N_BHALF);
    CP_COMMIT();
    __syncthreads();

    {
        const float4* f4 = reinterpret_cast<const float4*>(feat);
        const float4* a4 = reinterpret_cast<const float4*>(g_agg);
        #pragma unroll
        for (int it = 0; it < 16; ++it) {
            int ci = tid + it * 512;
            int r  = ci >> 6;
            int c4 = ci & 63;
            int node = tile0 + r;
            float4 v = make_float4(0.f, 0.f, 0.f, 0.f);
            if (node < NN)
                v = (c4 < 32) ? a4[(size_t)node * 32 + c4]
                              : f4[(size_t)node * 32 + (c4 - 32)];
            split_store(smc, SM_AHI, SM_ALO, r * AROW + c4 * 8, v);
        }
    }
    __syncthreads();

    float acc[2][8][4];
    #pragma unroll
    for (int m = 0; m < 2; ++m)
        #pragma unroll
        for (int n = 0; n < 8; ++n)
            #pragma unroll
            for (int q = 0; q < 4; ++q) acc[m][n][q] = 0.f;

    for (int c = 0; c < 8; ++c) {
        if (c < 7)
            stage_b(sb + SM_B + (uint32_t)((c + 1) & 1) * N_BBUF, tid,
                    g_uW0h, g_uW0l, 0, c + 1, 256, HH, N_BHALF);
        CP_COMMIT();
        CP_WAIT(1);
        __syncthreads();
        const uint32_t bbase = sb + SM_B + (uint32_t)(c & 1) * N_BBUF;
        #pragma unroll
        for (int ks = 0; ks < 2; ++ks) {
            const int kA = c * 32 + ks * 16;
            uint32_t ah[2][4], al[2][4];
            #pragma unroll
            for (int mt = 0; mt < 2; ++mt) {
                uint32_t aaddr = sb + SM_AHI +
                    (uint32_t)((wr * 32 + mt * 16 + lrow) * AROW + (kA + lcol) * 2);
                ldsm_x4(ah[mt][0], ah[mt][1], ah[mt][2], ah[mt][3], aaddr);
                ldsm_x4(al[mt][0], al[mt][1], al[mt][2], al[mt][3],
                        aaddr + (SM_ALO - SM_AHI));
            }
            #pragma unroll
            for (int np = 0; np < 4; ++np) {
                uint32_t baddr = bbase +
                    (uint32_t)((wc * 64 + np * 16 + lrow) * 80 + (ks * 16 + lcol) * 2);
                uint32_t bh0, bh1, bh2, bh3, bl0, bl1, bl2, bl3;
                ldsm_x4(bh0, bh1, bh2, bh3, baddr);
                ldsm_x4(bl0, bl1, bl2, bl3, baddr + N_BHALF);
                const int nb = np * 2;
                #pragma unroll
                for (int mt = 0; mt < 2; ++mt) {
                    mma_bf16(acc[mt][nb],     ah[mt], bh0, bh2);
                    mma_bf16(acc[mt][nb + 1], ah[mt], bh1, bh3);
                    mma_bf16(acc[mt][nb],     al[mt], bh0, bh2);
                    mma_bf16(acc[mt][nb + 1], al[mt], bh1, bh3);
                    mma_bf16(acc[mt][nb],     ah[mt], bl0, bl2);
                    mma_bf16(acc[mt][nb + 1], ah[mt], bl1, bl3);
                }
            }
        }
        __syncthreads();
    }

    stage_b(sb + SM_B, tid, g_uW1h, g_uW1l, 0, 0, 128, HH, N_BHALF);
    CP_COMMIT();

    #pragma unroll
    for (int mt = 0; mt < 2; ++mt)
        #pragma unroll
        for (int nt = 0; nt < 8; ++nt) {
            int cc = wc * 64 + nt * 8 + 2 * (lane & 3);
            int r0 = wr * 32 + mt * 16 + (lane >> 2);
            float* d = acc[mt][nt];
            float v0 = fmaxf(d[0] + b0s[cc], 0.f), v1 = fmaxf(d[1] + b0s[cc + 1], 0.f);
            float v2 = fmaxf(d[2] + b0s[cc], 0.f), v3 = fmaxf(d[3] + b0s[cc + 1], 0.f);
            __nv_bfloat16 h0 = __float2bfloat16(v0), h1 = __float2bfloat16(v1);
            __nv_bfloat16 h2 = __float2bfloat16(v2), h3 = __float2bfloat16(v3);
            int o0 = r0 * AROW + cc * 2;
            int o1 = (r0 + 8) * AROW + cc * 2;
            *reinterpret_cast<uint32_t*>(smc + SM_AHI + o0) = pack_bf16(v0, v1);
            *reinterpret_cast<uint32_t*>(smc + SM_AHI + o1) = pack_bf16(v2, v3);
            *reinterpret_cast<uint32_t*>(smc + SM_ALO + o0) =
                pack_bf16(v0 - __bfloat162float(h0), v1 - __bfloat162float(h1));
            *reinterpret_cast<uint32_t*>(smc + SM_ALO + o1) =
                pack_bf16(v2 - __bfloat162float(h2), v3 - __bfloat162float(h3));
        }

    float ac2[2][4][4];
    #pragma unroll
    for (int m = 0; m < 2; ++m)
        #pragma unroll
        for (int n = 0; n < 4; ++n)
            #pragma unroll
            for (int q = 0; q < 4; ++q) ac2[m][n][q] = 0.f;

    for (int c = 0; c < 8; ++c) {
        if (c < 7)
            stage_b(sb + SM_B + (uint32_t)((c + 1) & 1) * N_BBUF, tid,
                    g_uW1h, g_uW1l, 0, c + 1, 128, HH, N_BHALF);
        CP_COMMIT();
        CP_WAIT(1);
        __syncthreads();
        const uint32_t bbase = sb + SM_B + (uint32_t)(c & 1) * N_BBUF;
        #pragma unroll
        for (int ks = 0; ks < 2; ++ks) {
            const int kA = c * 32 + ks * 16;
            uint32_t ah[2][4], al[2][4];
            #pragma unroll
            for (int mt = 0; mt < 2; ++mt) {
                uint32_t aaddr = sb + SM_AHI +
                    (uint32_t)((wr * 32 + mt * 16 + lrow) * AROW + (kA + lcol) * 2);
                ldsm_x4(ah[mt][0], ah[mt][1], ah[mt][2], ah[mt][3], aaddr);
                ldsm_x4(al[mt][0], al[mt][1], al[mt][2], al[mt][3],
                        aaddr + (SM_ALO - SM_AHI));
            }
            #pragma unroll
            for (int np = 0; np < 2; ++np) {
                uint32_t baddr = bbase +
                    (uint32_t)((wc * 32 + np * 16 + lrow) * 80 + (ks * 16 + lcol) * 2);
                uint32_t bh0, bh1, bh2, bh3, bl0, bl1, bl2, bl3;
                ldsm_x4(bh0, bh1, bh2, bh3, baddr);
                ldsm_x4(bl0, bl1, bl2, bl3, baddr + N_BHALF);
                const int nb = np * 2;
                #pragma unroll
                for (int mt = 0; mt < 2; ++mt) {
                    mma_bf16(ac2[mt][nb],     ah[mt], bh0, bh2);
                    mma_bf16(ac2[mt][nb + 1], ah[mt], bh1, bh3);
                    mma_bf16(ac2[mt][nb],     al[mt], bh0, bh2);
                    mma_bf16(ac2[mt][nb + 1], al[mt], bh1, bh3);
                    mma_bf16(ac2[mt][nb],     ah[mt], bl0, bl2);
                    mma_bf16(ac2[mt][nb + 1], ah[mt], bl1, bl3);
                }
            }
        }
        __syncthreads();
    }

    #pragma unroll
    for (int mt = 0; mt < 2; ++mt)
        #pragma unroll
        for (int nt = 0; nt < 4; ++nt) {
            int cc = wc * 32 + nt * 8 + 2 * (lane & 3);
            int r0 = wr * 32 + mt * 16 + (lane >> 2);
            int r1 = r0 + 8;
            float* d = ac2[mt][nt];
            float v0 = fmaxf(d[0] + b1s[cc], 0.f), v1 = fmaxf(d[1] + b1s[cc + 1], 0.f);
            float v2 = fmaxf(d[2] + b1s[cc], 0.f), v3 = fmaxf(d[3] + b1s[cc + 1], 0.f);
            int n0 = tile0 + r0, n1 = tile0 + r1;
            if (n0 < NN) {
                float2 f = *reinterpret_cast<const float2*>(feat + (size_t)n0 * DD + cc);
                *reinterpret_cast<float2*>(outp + (size_t)n0 * DD + cc) =
                    make_float2(f.x + v0, f.y + v1);
            }
            if (n1 < NN) {
                float2 f = *reinterpret_cast<const float2*>(feat + (size_t)n1 * DD + cc);
                *reinterpret_cast<float2*>(outp + (size_t)n1 * DD + cc) =
                    make_float2(f.x + v2, f.y + v3);
            }
        }
}

// ============================== host launch =================================
extern "C" void kernel_launch(void* const* d_in, const int* in_sizes, int n_in,
                              void* d_out, int out_size)
{
    const float* feat  = (const float*)d_in[0];
    const int*   f_idx = (const int*)  d_in[1];
    const int*   t_idx = (const int*)  d_in[2];
    const float* msgW0 = (const float*)d_in[3];
    const float* msgb0 = (const float*)d_in[4];
    const float* msgW1 = (const float*)d_in[5];
    const float* msgb1 = (const float*)d_in[6];
    const float* updW0 = (const float*)d_in[7];
    const float* updb0 = (const float*)d_in[8];
    const float* updW1 = (const float*)d_in[9];
    const float* updb1 = (const float*)d_in[10];
    float* out = (float*)d_out;

    cudaFuncSetAttribute(pq_kernel,   cudaFuncAttributeMaxDynamicSharedMemorySize, P_SMEM);
    cudaFuncSetAttribute(edge_kernel, cudaFuncAttributeMaxDynamicSharedMemorySize, E_SMEM);
    cudaFuncSetAttribute(node_kernel, cudaFuncAttributeMaxDynamicSharedMemorySize, N_SMEM);

    conv_w_kernel<<<768, 256>>>(msgW0, updW0, msgW1, updW1);
    zero_agg_kernel<<<1024, 256>>>();

    const int pq_tiles   = (NN + TM - 1) / TM;  // 391
    const int node_tiles = (NN + TM - 1) / TM;  // 391

    pq_kernel<<<pq_tiles, 512, P_SMEM>>>(feat, msgb0);
    edge_kernel<<<152, 512, E_SMEM>>>(f_idx, t_idx, msgb1);
    node_kernel<<<node_tiles, 512, N_SMEM>>>(feat, updb0, updb1, out);
}

// round 10
// speedup vs baseline: 1.4673x; 1.4673x over previous
#include <cuda_runtime.h>
#include <cuda_bf16.h>
#include <cstdint>
#include <cstddef>

#define NN 50000
#define NE 600000
#define DD 128
#define HH 256
#define TM 128

// ============================ device scratch ================================
__device__ float g_agg[(size_t)NN * DD];
__device__ float g_PQ[(size_t)NN * 512];    // per-node [P|Q]: P=feat@W0a+b0, Q=feat@W0b
// weights transposed to [N][K] row-major, bf16 hi/lo split
__device__ __nv_bfloat16 g_c0h[512 * DD],  g_c0l[512 * DD];   // msg [W0a|W0b]^T : [512][128]
__device__ __nv_bfloat16 g_mW1h[DD * HH],  g_mW1l[DD * HH];   // msg W1^T: [128][256]
__device__ __nv_bfloat16 g_uW0h[HH * HH],  g_uW0l[HH * HH];   // upd W0^T: [256][256]
__device__ __nv_bfloat16 g_uW1h[DD * HH],  g_uW1l[DD * HH];   // upd W1^T: [128][256]

// ============================ PTX helpers ===================================
__device__ __forceinline__ uint32_t smem_u32(const void* p) {
    uint32_t a;
    asm("{ .reg .u64 t; cvta.to.shared.u64 t, %1; cvt.u32.u64 %0, t; }" : "=r"(a) : "l"(p));
    return a;
}
__device__ __forceinline__ void ldsm_x4(uint32_t& r0, uint32_t& r1, uint32_t& r2,
                                        uint32_t& r3, uint32_t addr) {
    asm volatile("ldmatrix.sync.aligned.m8n8.x4.shared.b16 {%0,%1,%2,%3}, [%4];"
                 : "=r"(r0), "=r"(r1), "=r"(r2), "=r"(r3) : "r"(addr));
}
__device__ __forceinline__ void mma_bf16(float* d, const uint32_t* a,
                                         uint32_t b0, uint32_t b1) {
    asm volatile(
        "mma.sync.aligned.m16n8k16.row.col.f32.bf16.bf16.f32 "
        "{%0,%1,%2,%3},{%4,%5,%6,%7},{%8,%9},{%0,%1,%2,%3};"
        : "+f"(d[0]), "+f"(d[1]), "+f"(d[2]), "+f"(d[3])
        : "r"(a[0]), "r"(a[1]), "r"(a[2]), "r"(a[3]), "r"(b0), "r"(b1));
}
__device__ __forceinline__ uint32_t pack_bf16(float a, float b) {
    __nv_bfloat162 t = __floats2bfloat162_rn(a, b);
    return *reinterpret_cast<uint32_t*>(&t);
}
__device__ __forceinline__ void cpa16(uint32_t dst, const void* src) {
    asm volatile("cp.async.cg.shared.global [%0], [%1], 16;"
                 :: "r"(dst), "l"(src) : "memory");
}
#define CP_COMMIT() asm volatile("cp.async.commit_group;" ::: "memory")
#define CP_WAIT(n)  asm volatile("cp.async.wait_group %0;" :: "n"(n) : "memory")
__device__ __forceinline__ void red_add2(float* a, float v0, float v1) {
    asm volatile("red.global.add.v2.f32 [%0], {%1, %2};"
                 :: "l"(a), "f"(v0), "f"(v1) : "memory");
}

// store float4 -> hi/lo bf16x2 pairs at byte offset off in two tiles
__device__ __forceinline__ void split_store(char* smc, int hi_base, int lo_base,
                                            int off, float4 v) {
    __nv_bfloat16 h0 = __float2bfloat16(v.x), h1 = __float2bfloat16(v.y);
    __nv_bfloat16 h2 = __float2bfloat16(v.z), h3 = __float2bfloat16(v.w);
    uint2 H, L;
    H.x = pack_bf16(v.x, v.y);
    H.y = pack_bf16(v.z, v.w);
    L.x = pack_bf16(v.x - __bfloat162float(h0), v.y - __bfloat162float(h1));
    L.y = pack_bf16(v.z - __bfloat162float(h2), v.w - __bfloat162float(h3));
    *reinterpret_cast<uint2*>(smc + hi_base + off) = H;
    *reinterpret_cast<uint2*>(smc + lo_base + off) = L;
}

__device__ __forceinline__ float4 relu_add4(float4 p, float4 q) {
    float4 v;
    v.x = fmaxf(p.x + q.x, 0.f);
    v.y = fmaxf(p.y + q.y, 0.f);
    v.z = fmaxf(p.z + q.z, 0.f);
    v.w = fmaxf(p.w + q.w, 0.f);
    return v;
}

// =========================== prelude kernels ================================
__global__ void zero_agg_kernel() {
    const size_t n4 = (size_t)NN * DD / 4;
    float4 z = make_float4(0.f, 0.f, 0.f, 0.f);
    for (size_t i = (size_t)blockIdx.x * blockDim.x + threadIdx.x; i < n4;
         i += (size_t)gridDim.x * blockDim.x)
        reinterpret_cast<float4*>(g_agg)[i] = z;
}

__device__ __forceinline__ void put_split(__nv_bfloat16* h, __nv_bfloat16* l,
                                          int idx, float w) {
    __nv_bfloat16 hi = __float2bfloat16(w);
    h[idx] = hi;
    l[idx] = __float2bfloat16(w - __bfloat162float(hi));
}

__global__ void conv_w_kernel(const float* __restrict__ mW0, const float* __restrict__ uW0,
                              const float* __restrict__ mW1, const float* __restrict__ uW1) {
    int i = blockIdx.x * blockDim.x + threadIdx.x;
    if (i >= 196608) return;
    if (i < 65536) {
        int n = i >> 7, k = i & 127;
        float w = (n < 256) ? mW0[k * HH + n] : mW0[(128 + k) * HH + (n - 256)];
        put_split(g_c0h, g_c0l, n * DD + k, w);
    } else if (i < 131072) {
        int j = i - 65536, k = j >> 8, n = j & 255;
        put_split(g_uW0h, g_uW0l, n * HH + k, uW0[j]);
    } else if (i < 163840) {
        int j = i - 131072, k = j >> 7, n = j & 127;
        put_split(g_mW1h, g_mW1l, n * HH + k, mW1[j]);
    } else {
        int j = i - 163840, k = j >> 7, n = j & 127;
        put_split(g_uW1h, g_uW1l, n * HH + k, uW1[j]);
    }
}

// generic B-chunk stager: nrows x 32 K-cols, BROW=80, 512 threads
__device__ __forceinline__ void stage_b(uint32_t bbase, int tid,
                                        const __nv_bfloat16* Wh,
                                        const __nv_bfloat16* Wl,
                                        int row_base, int chunk, int nrows,
                                        int kstride, int bhalf) {
    #pragma unroll
    for (int i = 0; i < 2; ++i) {
        int idx = tid + i * 512;
        if (idx < nrows * 4) {
            int row = idx >> 2, seg = idx & 3;
            uint32_t d = bbase + (uint32_t)(row * 80 + seg * 16);
            const int so = (row_base + row) * kstride + chunk * 32 + seg * 8;
            cpa16(d, Wh + so);
            cpa16(d + bhalf, Wl + so);
        }
    }
}

// ======================= PQ precompute kernel ===============================
#define P_B0   0
#define P_AHI  4096
#define P_ALO  (4096 + 34816)           // 38912
#define P_B    (38912 + 34816)          // 73728
#define P_BHALF 20480
#define P_BBUF  40960
#define P_SMEM  (73728 + 2 * P_BBUF)    // 155648
#define AROW2  272

__global__ void __launch_bounds__(512, 1) pq_kernel(const float* __restrict__ feat,
                                                    const float* __restrict__ b0) {
    extern __shared__ char smc[];
    const uint32_t sb = smem_u32(smc);
    const int tid  = threadIdx.x;
    const int wid  = tid >> 5;
    const int lane = tid & 31;
    const int wr   = wid & 3;
    const int wc   = wid >> 2;
    const int lrow = ((lane >> 3) & 1) * 8 + (lane & 7);
    const int lcol = (lane >> 4) * 8;
    float* b0s = reinterpret_cast<float*>(smc + P_B0);

    const int tile0 = blockIdx.x * TM;
    if (tid < 256) b0s[tid] = b0[tid];

    stage_b(sb + P_B, tid, g_c0h, g_c0l, 0, 0, 256, DD, P_BHALF);
    CP_COMMIT();

    {
        const float4* f4 = reinterpret_cast<const float4*>(feat);
        #pragma unroll
        for (int it = 0; it < 8; ++it) {
            int ci = tid + it * 512;
            int r  = ci >> 5;
            int c4 = ci & 31;
            int node = tile0 + r;
            float4 v = make_float4(0.f, 0.f, 0.f, 0.f);
            if (node < NN) v = f4[(size_t)node * 32 + c4];
            split_store(smc, P_AHI, P_ALO, r * AROW2 + c4 * 8, v);
        }
    }
    __syncthreads();

    for (int h = 0; h < 2; ++h) {
        float acc[2][8][4];
        #pragma unroll
        for (int m = 0; m < 2; ++m)
            #pragma unroll
            for (int n = 0; n < 8; ++n)
                #pragma unroll
                for (int q = 0; q < 4; ++q) acc[m][n][q] = 0.f;

        for (int c = 0; c < 4; ++c) {
            int g = h * 4 + c;
            if (g < 7)
                stage_b(sb + P_B + (uint32_t)((g + 1) & 1) * P_BBUF, tid,
                        g_c0h, g_c0l, ((g + 1) >> 2) * 256, (g + 1) & 3, 256, DD, P_BHALF);
            CP_COMMIT();
            CP_WAIT(1);
            __syncthreads();
            const uint32_t bbase = sb + P_B + (uint32_t)(g & 1) * P_BBUF;
            #pragma unroll
            for (int ks = 0; ks < 2; ++ks) {
                const int kA = c * 32 + ks * 16;
                uint32_t ah[2][4], al[2][4];
                #pragma unroll
                for (int mt = 0; mt < 2; ++mt) {
                    uint32_t aaddr = sb + P_AHI +
                        (uint32_t)((wr * 32 + mt * 16 + lrow) * AROW2 + (kA + lcol) * 2);
                    ldsm_x4(ah[mt][0], ah[mt][1], ah[mt][2], ah[mt][3], aaddr);
                    ldsm_x4(al[mt][0], al[mt][1], al[mt][2], al[mt][3],
                            aaddr + (P_ALO - P_AHI));
                }
                #pragma unroll
                for (int np = 0; np < 4; ++np) {
                    uint32_t baddr = bbase +
                        (uint32_t)((wc * 64 + np * 16 + lrow) * 80 + (ks * 16 + lcol) * 2);
                    uint32_t bh0, bh1, bh2, bh3, bl0, bl1, bl2, bl3;
                    ldsm_x4(bh0, bh1, bh2, bh3, baddr);
                    ldsm_x4(bl0, bl1, bl2, bl3, baddr + P_BHALF);
                    const int nb = np * 2;
                    #pragma unroll
                    for (int mt = 0; mt < 2; ++mt) {
                        mma_bf16(acc[mt][nb],     ah[mt], bh0, bh2);
                        mma_bf16(acc[mt][nb + 1], ah[mt], bh1, bh3);
                        mma_bf16(acc[mt][nb],     al[mt], bh0, bh2);
                        mma_bf16(acc[mt][nb + 1], al[mt], bh1, bh3);
                        mma_bf16(acc[mt][nb],     ah[mt], bl0, bl2);
                        mma_bf16(acc[mt][nb + 1], ah[mt], bl1, bl3);
                    }
                }
            }
            __syncthreads();
        }

        #pragma unroll
        for (int mt = 0; mt < 2; ++mt)
            #pragma unroll
            for (int nt = 0; nt < 8; ++nt) {
                int cc = wc * 64 + nt * 8 + 2 * (lane & 3);
                int r0 = wr * 32 + mt * 16 + (lane >> 2);
                int r1 = r0 + 8;
                float* d = acc[mt][nt];
                float bb0 = (h == 0) ? b0s[cc] : 0.f;
                float bb1 = (h == 0) ? b0s[cc + 1] : 0.f;
                int n0 = tile0 + r0, n1 = tile0 + r1;
                if (n0 < NN)
                    *reinterpret_cast<float2*>(g_PQ + (size_t)n0 * 512 + h * 256 + cc) =
                        make_float2(d[0] + bb0, d[1] + bb1);
                if (n1 < NN)
                    *reinterpret_cast<float2*>(g_PQ + (size_t)n1 * 512 + h * 256 + cc) =
                        make_float2(d[2] + bb0, d[3] + bb1);
            }
    }
}

// ============================ edge kernel (persistent) ======================
// H chunks = relu(P[from] + Q[to]) produced on the fly; W1 smem-resident.
// All 16 warps: gather (reg-prefetched) -> convert -> MMA; v2 red epilogue.
#define E_B1   0                       // 128 floats
#define E_TO0  512                     // 128 ints (tile parity 0)
#define E_TO1  1024                    // 128 ints (tile parity 1)
#define E_A    4096                    // 2 A-chunk buffers: hi 10240 + lo 10240 each
#define E_B    (4096 + 40960)          // 45056; B hi: 8 chunks * 10240; lo at +81920
#define E_SMEM (45056 + 163840)        // 208896

#define EDGE_TILES ((NE + TM - 1) / TM)

__global__ void __launch_bounds__(512, 1) edge_kernel(
    const int* __restrict__ from_idx, const int* __restrict__ to_idx,
    const float* __restrict__ b1)
{
    extern __shared__ char smc[];
    const uint32_t sb = smem_u32(smc);
    const int tid  = threadIdx.x;
    const int wid  = tid >> 5;
    const int lane = tid & 31;
    const int wr   = wid & 3;
    const int wc   = wid >> 2;            // 0..3
    const int lrow = ((lane >> 3) & 1) * 8 + (lane & 7);
    const int lcol = (lane >> 4) * 8;

    float* b1s = reinterpret_cast<float*>(smc + E_B1);
    if (tid < 128) b1s[tid] = b1[tid];

    // ---- stage resident W1 hi/lo once ----
    #pragma unroll
    for (int i = 0; i < 8; ++i) {
        int idx = tid + i * 512;          // c*512 + row*4 + seg
        int c = idx >> 9, rs = idx & 511;
        int row = rs >> 2, seg = rs & 3;
        uint32_t d = sb + E_B + (uint32_t)(c * 10240 + row * 80 + seg * 16);
        int so = row * HH + c * 32 + seg * 8;
        cpa16(d, g_mW1h + so);
        cpa16(d + 81920, g_mW1l + so);
    }
    CP_COMMIT();
    CP_WAIT(0);
    __syncthreads();

    const float4* pq4 = reinterpret_cast<const float4*>(g_PQ);
    const int r  = tid >> 2;              // 0..127 (row this thread produces)
    const int sg = tid & 3;               // seg: 2 float4 per seg

    int tcnt = 0;
    for (int tile = blockIdx.x; tile < EDGE_TILES; tile += gridDim.x, ++tcnt) {
        const int tile0 = tile * TM;
        const int rem   = min(TM, NE - tile0);

        // per-row indices via direct LDG (L2-hit); sto double-buffered in smem
        int fr = (r < rem) ? from_idx[tile0 + r] : 0;
        int to = (r < rem) ? to_idx[tile0 + r]   : 0;
        int* stob = reinterpret_cast<int*>(smc + E_TO0 + (tcnt & 1) * 512);
        if (sg == 0) stob[r] = to;

        const size_t prow = (size_t)fr * 128 + sg * 2;        // float4 units
        const size_t qrow = (size_t)to * 128 + 64 + sg * 2;

        // produce chunk 0 into buf 0
        {
            float4 p0 = pq4[prow], p1 = pq4[prow + 1];
            float4 q0 = pq4[qrow], q1 = pq4[qrow + 1];
            int off = r * 80 + sg * 16;
            split_store(smc, E_A, E_A + 10240, off,     relu_add4(p0, q0));
            split_store(smc, E_A, E_A + 10240, off + 8, relu_add4(p1, q1));
        }
        __syncthreads();

        float ac2[2][4][4];
        #pragma unroll
        for (int m = 0; m < 2; ++m)
            #pragma unroll
            for (int n = 0; n < 4; ++n)
                #pragma unroll
                for (int q = 0; q < 4; ++q) ac2[m][n][q] = 0.f;

        #pragma unroll
        for (int c = 0; c < 8; ++c) {
            // issue next chunk's gathers (latency hidden by MMA below)
            float4 p0, p1, q0, q1;
            if (c < 7) {
                p0 = pq4[prow + (c + 1) * 8];
                p1 = pq4[prow + (c + 1) * 8 + 1];
                q0 = pq4[qrow + (c + 1) * 8];
                q1 = pq4[qrow + (c + 1) * 8 + 1];
            }
            const uint32_t abase = sb + E_A + (uint32_t)((c & 1) * 20480);
            const uint32_t bbase = sb + E_B + (uint32_t)(c * 10240);
            #pragma unroll
            for (int ks = 0; ks < 2; ++ks) {
                uint32_t ah[2][4], al[2][4];
                #pragma unroll
                for (int mt = 0; mt < 2; ++mt) {
                    uint32_t aaddr = abase +
                        (uint32_t)((wr * 32 + mt * 16 + lrow) * 80 + (ks * 16 + lcol) * 2);
                    ldsm_x4(ah[mt][0], ah[mt][1], ah[mt][2], ah[mt][3], aaddr);
                    ldsm_x4(al[mt][0], al[mt][1], al[mt][2], al[mt][3], aaddr + 10240);
                }
                #pragma unroll
                for (int np = 0; np < 2; ++np) {
                    uint32_t baddr = bbase +
                        (uint32_t)((wc * 32 + np * 16 + lrow) * 80 + (ks * 16 + lcol) * 2);
                    uint32_t bh0, bh1, bh2, bh3, bl0, bl1, bl2, bl3;
                    ldsm_x4(bh0, bh1, bh2, bh3, baddr);
                    ldsm_x4(bl0, bl1, bl2, bl3, baddr + 81920);
                    const int nb = np * 2;
                    #pragma unroll
                    for (int mt = 0; mt < 2; ++mt) {
                        mma_bf16(ac2[mt][nb],     ah[mt], bh0, bh2);
                        mma_bf16(ac2[mt][nb + 1], ah[mt], bh1, bh3);
                        mma_bf16(ac2[mt][nb],     al[mt], bh0, bh2);
                        mma_bf16(ac2[mt][nb + 1], al[mt], bh1, bh3);
                        mma_bf16(ac2[mt][nb],     ah[mt], bl0, bl2);
                        mma_bf16(ac2[mt][nb + 1], ah[mt], bl1, bl3);
                    }
                }
            }
            // convert + store next chunk into the other buffer
            if (c < 7) {
                const int ab = E_A + ((c + 1) & 1) * 20480;
                int off = r * 80 + sg * 16;
                split_store(smc, ab, ab + 10240, off,     relu_add4(p0, q0));
                split_store(smc, ab, ab + 10240, off + 8, relu_add4(p1, q1));
            }
            __syncthreads();
        }

        // ---- epilogue: bias+relu, vectorized red scatter ----
        const int* stor = reinterpret_cast<const int*>(smc + E_TO0 + (tcnt & 1) * 512);
        #pragma unroll
        for (int mt = 0; mt < 2; ++mt)
            #pragma unroll
            for (int nt = 0; nt < 4; ++nt) {
                int cc = wc * 32 + nt * 8 + 2 * (lane & 3);
                int r0 = wr * 32 + mt * 16 + (lane >> 2);
                int r1 = r0 + 8;
                float* d = ac2[mt][nt];
                float v0 = fmaxf(d[0] + b1s[cc], 0.f), v1 = fmaxf(d[1] + b1s[cc + 1], 0.f);
                float v2 = fmaxf(d[2] + b1s[cc], 0.f), v3 = fmaxf(d[3] + b1s[cc + 1], 0.f);
                if (r0 < rem)
                    red_add2(g_agg + (size_t)stor[r0] * DD + cc, v0, v1);
                if (r1 < rem)
                    red_add2(g_agg + (size_t)stor[r1] * DD + cc, v2, v3);
            }
    }
}

// ============================ node kernel ===================================
#define SM_B0   0
#define SM_B1   1024
#define SM_AHI  4096
#define SM_ALO  (4096 + 67584)          // 71680
#define SM_B    (71680 + 67584)         // 139264
#define N_BHALF 20480
#define N_BBUF  40960
#define N_SMEM  (139264 + 2 * N_BBUF)   // 221184
#define AROW 528

__global__ void __launch_bounds__(512, 1) node_kernel(
    const float* __restrict__ feat,
    const float* __restrict__ b0, const float* __restrict__ b1,
    float* __restrict__ outp)
{
    extern __shared__ char smc[];
    const uint32_t sb = smem_u32(smc);
    const int tid  = threadIdx.x;
    const int wid  = tid >> 5;
    const int lane = tid & 31;
    const int wr   = wid & 3;
    const int wc   = wid >> 2;
    const int lrow = ((lane >> 3) & 1) * 8 + (lane & 7);
    const int lcol = (lane >> 4) * 8;

    float* b0s = reinterpret_cast<float*>(smc + SM_B0);
    float* b1s = reinterpret_cast<float*>(smc + SM_B1);

    const int tile0 = blockIdx.x * TM;

    if (tid < 256) b0s[tid] = b0[tid];
    if (tid >= 256 && tid < 384) b1s[tid - 256] = b1[tid - 256];

    stage_b(sb + SM_B, tid, g_uW0h, g_uW0l, 0, 0, 256, HH, N_BHALF);
    CP_COMMIT();
    __syncthreads();

    {
        const float4* f4 = reinterpret_cast<const float4*>(feat);
        const float4* a4 = reinterpret_cast<const float4*>(g_agg);
        #pragma unroll
        for (int it = 0; it < 16; ++it) {
            int ci = tid + it * 512;
            int r  = ci >> 6;
            int c4 = ci & 63;
            int node = tile0 + r;
            float4 v = make_float4(0.f, 0.f, 0.f, 0.f);
            if (node < NN)
                v = (c4 < 32) ? a4[(size_t)node * 32 + c4]
                              : f4[(size_t)node * 32 + (c4 - 32)];
            split_store(smc, SM_AHI, SM_ALO, r * AROW + c4 * 8, v);
        }
    }
    __syncthreads();

    float acc[2][8][4];
    #pragma unroll
    for (int m = 0; m < 2; ++m)
        #pragma unroll
        for (int n = 0; n < 8; ++n)
            #pragma unroll
            for (int q = 0; q < 4; ++q) acc[m][n][q] = 0.f;

    for (int c = 0; c < 8; ++c) {
        if (c < 7)
            stage_b(sb + SM_B + (uint32_t)((c + 1) & 1) * N_BBUF, tid,
                    g_uW0h, g_uW0l, 0, c + 1, 256, HH, N_BHALF);
        CP_COMMIT();
        CP_WAIT(1);
        __syncthreads();
        const uint32_t bbase = sb + SM_B + (uint32_t)(c & 1) * N_BBUF;
        #pragma unroll
        for (int ks = 0; ks < 2; ++ks) {
            const int kA = c * 32 + ks * 16;
            uint32_t ah[2][4], al[2][4];
            #pragma unroll
            for (int mt = 0; mt < 2; ++mt) {
                uint32_t aaddr = sb + SM_AHI +
                    (uint32_t)((wr * 32 + mt * 16 + lrow) * AROW + (kA + lcol) * 2);
                ldsm_x4(ah[mt][0], ah[mt][1], ah[mt][2], ah[mt][3], aaddr);
                ldsm_x4(al[mt][0], al[mt][1], al[mt][2], al[mt][3],
                        aaddr + (SM_ALO - SM_AHI));
            }
            #pragma unroll
            for (int np = 0; np < 4; ++np) {
                uint32_t baddr = bbase +
                    (uint32_t)((wc * 64 + np * 16 + lrow) * 80 + (ks * 16 + lcol) * 2);
                uint32_t bh0, bh1, bh2, bh3, bl0, bl1, bl2, bl3;
                ldsm_x4(bh0, bh1, bh2, bh3, baddr);
                ldsm_x4(bl0, bl1, bl2, bl3, baddr + N_BHALF);
                const int nb = np * 2;
                #pragma unroll
                for (int mt = 0; mt < 2; ++mt) {
                    mma_bf16(acc[mt][nb],     ah[mt], bh0, bh2);
                    mma_bf16(acc[mt][nb + 1], ah[mt], bh1, bh3);
                    mma_bf16(acc[mt][nb],     al[mt], bh0, bh2);
                    mma_bf16(acc[mt][nb + 1], al[mt], bh1, bh3);
                    mma_bf16(acc[mt][nb],     ah[mt], bl0, bl2);
                    mma_bf16(acc[mt][nb + 1], ah[mt], bl1, bl3);
                }
            }
        }
        __syncthreads();
    }

    stage_b(sb + SM_B, tid, g_uW1h, g_uW1l, 0, 0, 128, HH, N_BHALF);
    CP_COMMIT();

    #pragma unroll
    for (int mt = 0; mt < 2; ++mt)
        #pragma unroll
        for (int nt = 0; nt < 8; ++nt) {
            int cc = wc * 64 + nt * 8 + 2 * (lane & 3);
            int r0 = wr * 32 + mt * 16 + (lane >> 2);
            float* d = acc[mt][nt];
            float v0 = fmaxf(d[0] + b0s[cc], 0.f), v1 = fmaxf(d[1] + b0s[cc + 1], 0.f);
            float v2 = fmaxf(d[2] + b0s[cc], 0.f), v3 = fmaxf(d[3] + b0s[cc + 1], 0.f);
            __nv_bfloat16 h0 = __float2bfloat16(v0), h1 = __float2bfloat16(v1);
            __nv_bfloat16 h2 = __float2bfloat16(v2), h3 = __float2bfloat16(v3);
            int o0 = r0 * AROW + cc * 2;
            int o1 = (r0 + 8) * AROW + cc * 2;
            *reinterpret_cast<uint32_t*>(smc + SM_AHI + o0) = pack_bf16(v0, v1);
            *reinterpret_cast<uint32_t*>(smc + SM_AHI + o1) = pack_bf16(v2, v3);
            *reinterpret_cast<uint32_t*>(smc + SM_ALO + o0) =
                pack_bf16(v0 - __bfloat162float(h0), v1 - __bfloat162float(h1));
            *reinterpret_cast<uint32_t*>(smc + SM_ALO + o1) =
                pack_bf16(v2 - __bfloat162float(h2), v3 - __bfloat162float(h3));
        }

    float ac2[2][4][4];
    #pragma unroll
    for (int m = 0; m < 2; ++m)
        #pragma unroll
        for (int n = 0; n < 4; ++n)
            #pragma unroll
            for (int q = 0; q < 4; ++q) ac2[m][n][q] = 0.f;

    for (int c = 0; c < 8; ++c) {
        if (c < 7)
            stage_b(sb + SM_B + (uint32_t)((c + 1) & 1) * N_BBUF, tid,
                    g_uW1h, g_uW1l, 0, c + 1, 128, HH, N_BHALF);
        CP_COMMIT();
        CP_WAIT(1);
        __syncthreads();
        const uint32_t bbase = sb + SM_B + (uint32_t)(c & 1) * N_BBUF;
        #pragma unroll
        for (int ks = 0; ks < 2; ++ks) {
            const int kA = c * 32 + ks * 16;
            uint32_t ah[2][4], al[2][4];
            #pragma unroll
            for (int mt = 0; mt < 2; ++mt) {
                uint32_t aaddr = sb + SM_AHI +
                    (uint32_t)((wr * 32 + mt * 16 + lrow) * AROW + (kA + lcol) * 2);
                ldsm_x4(ah[mt][0], ah[mt][1], ah[mt][2], ah[mt][3], aaddr);
                ldsm_x4(al[mt][0], al[mt][1], al[mt][2], al[mt][3],
                        aaddr + (SM_ALO - SM_AHI));
            }
            #pragma unroll
            for (int np = 0; np < 2; ++np) {
                uint32_t baddr = bbase +
                    (uint32_t)((wc * 32 + np * 16 + lrow) * 80 + (ks * 16 + lcol) * 2);
                uint32_t bh0, bh1, bh2, bh3, bl0, bl1, bl2, bl3;
                ldsm_x4(bh0, bh1, bh2, bh3, baddr);
                ldsm_x4(bl0, bl1, bl2, bl3, baddr + N_BHALF);
                const int nb = np * 2;
                #pragma unroll
                for (int mt = 0; mt < 2; ++mt) {
                    mma_bf16(ac2[mt][nb],     ah[mt], bh0, bh2);
                    mma_bf16(ac2[mt][nb + 1], ah[mt], bh1, bh3);
                    mma_bf16(ac2[mt][nb],     al[mt], bh0, bh2);
                    mma_bf16(ac2[mt][nb + 1], al[mt], bh1, bh3);
                    mma_bf16(ac2[mt][nb],     ah[mt], bl0, bl2);
                    mma_bf16(ac2[mt][nb + 1], ah[mt], bl1, bl3);
                }
            }
        }
        __syncthreads();
    }

    #pragma unroll
    for (int mt = 0; mt < 2; ++mt)
        #pragma unroll
        for (int nt = 0; nt < 4; ++nt) {
            int cc = wc * 32 + nt * 8 + 2 * (lane & 3);
            int r0 = wr * 32 + mt * 16 + (lane >> 2);
            int r1 = r0 + 8;
            float* d = ac2[mt][nt];
            float v0 = fmaxf(d[0] + b1s[cc], 0.f), v1 = fmaxf(d[1] + b1s[cc + 1], 0.f);
            float v2 = fmaxf(d[2] + b1s[cc], 0.f), v3 = fmaxf(d[3] + b1s[cc + 1], 0.f);
            int n0 = tile0 + r0, n1 = tile0 + r1;
            if (n0 < NN) {
                float2 f = *reinterpret_cast<const float2*>(feat + (size_t)n0 * DD + cc);
                *reinterpret_cast<float2*>(outp + (size_t)n0 * DD + cc) =
                    make_float2(f.x + v0, f.y + v1);
            }
            if (n1 < NN) {
                float2 f = *reinterpret_cast<const float2*>(feat + (size_t)n1 * DD + cc);
                *reinterpret_cast<float2*>(outp + (size_t)n1 * DD + cc) =
                    make_float2(f.x + v2, f.y + v3);
            }
        }
}

// ============================== host launch =================================
extern "C" void kernel_launch(void* const* d_in, const int* in_sizes, int n_in,
                              void* d_out, int out_size)
{
    const float* feat  = (const float*)d_in[0];
    const int*   f_idx = (const int*)  d_in[1];
    const int*   t_idx = (const int*)  d_in[2];
    const float* msgW0 = (const float*)d_in[3];
    const float* msgb0 = (const float*)d_in[4];
    const float* msgW1 = (const float*)d_in[5];
    const float* msgb1 = (const float*)d_in[6];
    const float* updW0 = (const float*)d_in[7];
    const float* updb0 = (const float*)d_in[8];
    const float* updW1 = (const float*)d_in[9];
    const float* updb1 = (const float*)d_in[10];
    float* out = (float*)d_out;

    cudaFuncSetAttribute(pq_kernel,   cudaFuncAttributeMaxDynamicSharedMemorySize, P_SMEM);
    cudaFuncSetAttribute(edge_kernel, cudaFuncAttributeMaxDynamicSharedMemorySize, E_SMEM);
    cudaFuncSetAttribute(node_kernel, cudaFuncAttributeMaxDynamicSharedMemorySize, N_SMEM);

    conv_w_kernel<<<768, 256>>>(msgW0, updW0, msgW1, updW1);
    zero_agg_kernel<<<1024, 256>>>();

    const int pq_tiles   = (NN + TM - 1) / TM;  // 391
    const int node_tiles = (NN + TM - 1) / TM;  // 391

    pq_kernel<<<pq_tiles, 512, P_SMEM>>>(feat, msgb0);
    edge_kernel<<<152, 512, E_SMEM>>>(f_idx, t_idx, msgb1);
    node_kernel<<<node_tiles, 512, N_SMEM>>>(feat, updb0, updb1, out);
}

// round 11
// speedup vs baseline: 1.7046x; 1.1617x over previous
#include <cuda_runtime.h>
#include <cuda_bf16.h>
#include <cstdint>
#include <cstddef>

#define NN 50000
#define NE 600000
#define DD 128
#define HH 256
#define TM 128

// ============================ device scratch ================================
__device__ float g_agg[(size_t)NN * DD];
__device__ float g_PQ[(size_t)NN * 512];    // per-node [P|Q]: P=feat@W0a+b0, Q=feat@W0b
// weights transposed to [N][K] row-major, bf16 hi/lo split
__device__ __nv_bfloat16 g_c0h[512 * DD],  g_c0l[512 * DD];   // msg [W0a|W0b]^T : [512][128]
__device__ __nv_bfloat16 g_mW1h[DD * HH],  g_mW1l[DD * HH];   // msg W1^T: [128][256]
__device__ __nv_bfloat16 g_uW0h[HH * HH],  g_uW0l[HH * HH];   // upd W0^T: [256][256]
__device__ __nv_bfloat16 g_uW1h[DD * HH],  g_uW1l[DD * HH];   // upd W1^T: [128][256]

// ============================ PTX helpers ===================================
__device__ __forceinline__ uint32_t smem_u32(const void* p) {
    uint32_t a;
    asm("{ .reg .u64 t; cvta.to.shared.u64 t, %1; cvt.u32.u64 %0, t; }" : "=r"(a) : "l"(p));
    return a;
}
__device__ __forceinline__ void ldsm_x4(uint32_t& r0, uint32_t& r1, uint32_t& r2,
                                        uint32_t& r3, uint32_t addr) {
    asm volatile("ldmatrix.sync.aligned.m8n8.x4.shared.b16 {%0,%1,%2,%3}, [%4];"
                 : "=r"(r0), "=r"(r1), "=r"(r2), "=r"(r3) : "r"(addr));
}
__device__ __forceinline__ void mma_bf16(float* d, const uint32_t* a,
                                         uint32_t b0, uint32_t b1) {
    asm volatile(
        "mma.sync.aligned.m16n8k16.row.col.f32.bf16.bf16.f32 "
        "{%0,%1,%2,%3},{%4,%5,%6,%7},{%8,%9},{%0,%1,%2,%3};"
        : "+f"(d[0]), "+f"(d[1]), "+f"(d[2]), "+f"(d[3])
        : "r"(a[0]), "r"(a[1]), "r"(a[2]), "r"(a[3]), "r"(b0), "r"(b1));
}
__device__ __forceinline__ uint32_t pack_bf16(float a, float b) {
    __nv_bfloat162 t = __floats2bfloat162_rn(a, b);
    return *reinterpret_cast<uint32_t*>(&t);
}
__device__ __forceinline__ void cpa16(uint32_t dst, const void* src) {
    asm volatile("cp.async.cg.shared.global [%0], [%1], 16;"
                 :: "r"(dst), "l"(src) : "memory");
}
#define CP_COMMIT() asm volatile("cp.async.commit_group;" ::: "memory")
#define CP_WAIT(n)  asm volatile("cp.async.wait_group %0;" :: "n"(n) : "memory")
__device__ __forceinline__ void red_add2(float* a, float v0, float v1) {
    asm volatile("red.global.add.v2.f32 [%0], {%1, %2};"
                 :: "l"(a), "f"(v0), "f"(v1) : "memory");
}
__device__ __forceinline__ void bar_half(int id) {
    asm volatile("bar.sync %0, 256;" :: "r"(id) : "memory");
}

// store float4 -> hi/lo bf16x2 pairs at byte offset off in two tiles
__device__ __forceinline__ void split_store(char* smc, int hi_base, int lo_base,
                                            int off, float4 v) {
    __nv_bfloat16 h0 = __float2bfloat16(v.x), h1 = __float2bfloat16(v.y);
    __nv_bfloat16 h2 = __float2bfloat16(v.z), h3 = __float2bfloat16(v.w);
    uint2 H, L;
    H.x = pack_bf16(v.x, v.y);
    H.y = pack_bf16(v.z, v.w);
    L.x = pack_bf16(v.x - __bfloat162float(h0), v.y - __bfloat162float(h1));
    L.y = pack_bf16(v.z - __bfloat162float(h2), v.w - __bfloat162float(h3));
    *reinterpret_cast<uint2*>(smc + hi_base + off) = H;
    *reinterpret_cast<uint2*>(smc + lo_base + off) = L;
}

__device__ __forceinline__ float4 relu_add4(float4 p, float4 q) {
    float4 v;
    v.x = fmaxf(p.x + q.x, 0.f);
    v.y = fmaxf(p.y + q.y, 0.f);
    v.z = fmaxf(p.z + q.z, 0.f);
    v.w = fmaxf(p.w + q.w, 0.f);
    return v;
}

// =========================== prelude kernels ================================
__global__ void zero_agg_kernel() {
    const size_t n4 = (size_t)NN * DD / 4;
    float4 z = make_float4(0.f, 0.f, 0.f, 0.f);
    for (size_t i = (size_t)blockIdx.x * blockDim.x + threadIdx.x; i < n4;
         i += (size_t)gridDim.x * blockDim.x)
        reinterpret_cast<float4*>(g_agg)[i] = z;
}

__device__ __forceinline__ void put_split(__nv_bfloat16* h, __nv_bfloat16* l,
                                          int idx, float w) {
    __nv_bfloat16 hi = __float2bfloat16(w);
    h[idx] = hi;
    l[idx] = __float2bfloat16(w - __bfloat162float(hi));
}

__global__ void conv_w_kernel(const float* __restrict__ mW0, const float* __restrict__ uW0,
                              const float* __restrict__ mW1, const float* __restrict__ uW1) {
    int i = blockIdx.x * blockDim.x + threadIdx.x;
    if (i >= 196608) return;
    if (i < 65536) {
        int n = i >> 7, k = i & 127;
        float w = (n < 256) ? mW0[k * HH + n] : mW0[(128 + k) * HH + (n - 256)];
        put_split(g_c0h, g_c0l, n * DD + k, w);
    } else if (i < 131072) {
        int j = i - 65536, k = j >> 8, n = j & 255;
        put_split(g_uW0h, g_uW0l, n * HH + k, uW0[j]);
    } else if (i < 163840) {
        int j = i - 131072, k = j >> 7, n = j & 127;
        put_split(g_mW1h, g_mW1l, n * HH + k, mW1[j]);
    } else {
        int j = i - 163840, k = j >> 7, n = j & 127;
        put_split(g_uW1h, g_uW1l, n * HH + k, uW1[j]);
    }
}

// generic B-chunk stager: nrows x 32 K-cols, BROW=80, 512 threads
__device__ __forceinline__ void stage_b(uint32_t bbase, int tid,
                                        const __nv_bfloat16* Wh,
                                        const __nv_bfloat16* Wl,
                                        int row_base, int chunk, int nrows,
                                        int kstride, int bhalf) {
    #pragma unroll
    for (int i = 0; i < 2; ++i) {
        int idx = tid + i * 512;
        if (idx < nrows * 4) {
            int row = idx >> 2, seg = idx & 3;
            uint32_t d = bbase + (uint32_t)(row * 80 + seg * 16);
            const int so = (row_base + row) * kstride + chunk * 32 + seg * 8;
            cpa16(d, Wh + so);
            cpa16(d + bhalf, Wl + so);
        }
    }
}

// ======================= PQ precompute kernel ===============================
#define P_B0   0
#define P_AHI  4096
#define P_ALO  (4096 + 34816)           // 38912
#define P_B    (38912 + 34816)          // 73728
#define P_BHALF 20480
#define P_BBUF  40960
#define P_SMEM  (73728 + 2 * P_BBUF)    // 155648
#define AROW2  272

__global__ void __launch_bounds__(512, 1) pq_kernel(const float* __restrict__ feat,
                                                    const float* __restrict__ b0) {
    extern __shared__ char smc[];
    const uint32_t sb = smem_u32(smc);
    const int tid  = threadIdx.x;
    const int wid  = tid >> 5;
    const int lane = tid & 31;
    const int wr   = wid & 3;
    const int wc   = wid >> 2;
    const int lrow = ((lane >> 3) & 1) * 8 + (lane & 7);
    const int lcol = (lane >> 4) * 8;
    float* b0s = reinterpret_cast<float*>(smc + P_B0);

    const int tile0 = blockIdx.x * TM;
    if (tid < 256) b0s[tid] = b0[tid];

    stage_b(sb + P_B, tid, g_c0h, g_c0l, 0, 0, 256, DD, P_BHALF);
    CP_COMMIT();

    {
        const float4* f4 = reinterpret_cast<const float4*>(feat);
        #pragma unroll
        for (int it = 0; it < 8; ++it) {
            int ci = tid + it * 512;
            int r  = ci >> 5;
            int c4 = ci & 31;
            int node = tile0 + r;
            float4 v = make_float4(0.f, 0.f, 0.f, 0.f);
            if (node < NN) v = f4[(size_t)node * 32 + c4];
            split_store(smc, P_AHI, P_ALO, r * AROW2 + c4 * 8, v);
        }
    }
    __syncthreads();

    for (int h = 0; h < 2; ++h) {
        float acc[2][8][4];
        #pragma unroll
        for (int m = 0; m < 2; ++m)
            #pragma unroll
            for (int n = 0; n < 8; ++n)
                #pragma unroll
                for (int q = 0; q < 4; ++q) acc[m][n][q] = 0.f;

        for (int c = 0; c < 4; ++c) {
            int g = h * 4 + c;
            if (g < 7)
                stage_b(sb + P_B + (uint32_t)((g + 1) & 1) * P_BBUF, tid,
                        g_c0h, g_c0l, ((g + 1) >> 2) * 256, (g + 1) & 3, 256, DD, P_BHALF);
            CP_COMMIT();
            CP_WAIT(1);
            __syncthreads();
            const uint32_t bbase = sb + P_B + (uint32_t)(g & 1) * P_BBUF;
            #pragma unroll
            for (int ks = 0; ks < 2; ++ks) {
                const int kA = c * 32 + ks * 16;
                uint32_t ah[2][4], al[2][4];
                #pragma unroll
                for (int mt = 0; mt < 2; ++mt) {
                    uint32_t aaddr = sb + P_AHI +
                        (uint32_t)((wr * 32 + mt * 16 + lrow) * AROW2 + (kA + lcol) * 2);
                    ldsm_x4(ah[mt][0], ah[mt][1], ah[mt][2], ah[mt][3], aaddr);
                    ldsm_x4(al[mt][0], al[mt][1], al[mt][2], al[mt][3],
                            aaddr + (P_ALO - P_AHI));
                }
                #pragma unroll
                for (int np = 0; np < 4; ++np) {
                    uint32_t baddr = bbase +
                        (uint32_t)((wc * 64 + np * 16 + lrow) * 80 + (ks * 16 + lcol) * 2);
                    uint32_t bh0, bh1, bh2, bh3, bl0, bl1, bl2, bl3;
                    ldsm_x4(bh0, bh1, bh2, bh3, baddr);
                    ldsm_x4(bl0, bl1, bl2, bl3, baddr + P_BHALF);
                    const int nb = np * 2;
                    #pragma unroll
                    for (int mt = 0; mt < 2; ++mt) {
                        mma_bf16(acc[mt][nb],     ah[mt], bh0, bh2);
                        mma_bf16(acc[mt][nb + 1], ah[mt], bh1, bh3);
                        mma_bf16(acc[mt][nb],     al[mt], bh0, bh2);
                        mma_bf16(acc[mt][nb + 1], al[mt], bh1, bh3);
                        mma_bf16(acc[mt][nb],     ah[mt], bl0, bl2);
                        mma_bf16(acc[mt][nb + 1], ah[mt], bl1, bl3);
                    }
                }
            }
            __syncthreads();
        }

        #pragma unroll
        for (int mt = 0; mt < 2; ++mt)
            #pragma unroll
            for (int nt = 0; nt < 8; ++nt) {
                int cc = wc * 64 + nt * 8 + 2 * (lane & 3);
                int r0 = wr * 32 + mt * 16 + (lane >> 2);
                int r1 = r0 + 8;
                float* d = acc[mt][nt];
                float bb0 = (h == 0) ? b0s[cc] : 0.f;
                float bb1 = (h == 0) ? b0s[cc + 1] : 0.f;
                int n0 = tile0 + r0, n1 = tile0 + r1;
                if (n0 < NN)
                    *reinterpret_cast<float2*>(g_PQ + (size_t)n0 * 512 + h * 256 + cc) =
                        make_float2(d[0] + bb0, d[1] + bb1);
                if (n1 < NN)
                    *reinterpret_cast<float2*>(g_PQ + (size_t)n1 * 512 + h * 256 + cc) =
                        make_float2(d[2] + bb0, d[3] + bb1);
            }
    }
}

// ============== edge kernel (persistent, two independent halves) ============
// Group g (warps 8g..8g+7, 256 thr) owns rows g*64..g*64+63 of each tile:
// own A double-buffers, own sto parity buffers, own named barrier (1+g).
// W1 smem-resident (read-only after init). Groups never sync after init.
#define E_B1   0                       // 128 floats
#define E_TO   512                     // 4 x 64 ints: [g][parity]
#define E_A    4096                    // per group: 2 bufs of (hi 5120 + lo 5120)
#define E_B    (4096 + 40960)          // 45056; B hi: 8 chunks * 10240; lo at +81920
#define E_SMEM (45056 + 163840)        // 208896

#define EDGE_TILES ((NE + TM - 1) / TM)

__global__ void __launch_bounds__(512, 1) edge_kernel(
    const int* __restrict__ from_idx, const int* __restrict__ to_idx,
    const float* __restrict__ b1)
{
    extern __shared__ char smc[];
    const uint32_t sb = smem_u32(smc);
    const int tid  = threadIdx.x;
    const int wid  = tid >> 5;
    const int lane = tid & 31;
    const int g    = wid >> 3;            // group 0/1
    const int gwid = wid & 7;             // warp within group
    const int wr   = gwid & 1;            // row group: rows wr*32..+32 (of 64)
    const int wc   = gwid >> 1;           // col group 0..3 (32 cols each)
    const int lrow = ((lane >> 3) & 1) * 8 + (lane & 7);
    const int lcol = (lane >> 4) * 8;
    const int barid = 1 + g;

    float* b1s = reinterpret_cast<float*>(smc + E_B1);
    if (tid < 128) b1s[tid] = b1[tid];

    // ---- stage resident W1 hi/lo once ----
    #pragma unroll
    for (int i = 0; i < 8; ++i) {
        int idx = tid + i * 512;          // c*512 + row*4 + seg
        int c = idx >> 9, rs = idx & 511;
        int row = rs >> 2, seg = rs & 3;
        uint32_t d = sb + E_B + (uint32_t)(c * 10240 + row * 80 + seg * 16);
        int so = row * HH + c * 32 + seg * 8;
        cpa16(d, g_mW1h + so);
        cpa16(d + 81920, g_mW1l + so);
    }
    CP_COMMIT();
    CP_WAIT(0);
    __syncthreads();                      // last full-CTA sync

    // hoist bias values into registers (constant across tiles)
    float bv0[4], bv1[4];
    #pragma unroll
    for (int nt = 0; nt < 4; ++nt) {
        int cc = wc * 32 + nt * 8 + 2 * (lane & 3);
        bv0[nt] = b1s[cc];
        bv1[nt] = b1s[cc + 1];
    }

    const float4* pq4 = reinterpret_cast<const float4*>(g_PQ);
    const int ptid = tid & 255;           // group-local thread id
    const int r  = ptid >> 2;             // local row 0..63
    const int sg = ptid & 3;              // seg: 2 float4 per seg
    const int grow = g * 64 + r;          // row within 128-edge tile

    int tcnt = 0;
    for (int tile = blockIdx.x; tile < EDGE_TILES; tile += gridDim.x, ++tcnt) {
        const int tile0 = tile * TM;
        const int rem   = min(TM, NE - tile0);

        // per-row indices via direct LDG; sto per-group parity buffers
        int fr = (grow < rem) ? from_idx[tile0 + grow] : 0;
        int to = (grow < rem) ? to_idx[tile0 + grow]   : 0;
        int* stob = reinterpret_cast<int*>(smc + E_TO + (g * 2 + (tcnt & 1)) * 256);
        if (sg == 0) stob[r] = to;

        const size_t prow = (size_t)fr * 128 + sg * 2;        // float4 units
        const size_t qrow = (size_t)to * 128 + 64 + sg * 2;
        const int ga = E_A + g * 20480;

        // produce chunk 0 into buf 0
        {
            float4 p0 = pq4[prow], p1 = pq4[prow + 1];
            float4 q0 = pq4[qrow], q1 = pq4[qrow + 1];
            int off = r * 80 + sg * 16;
            split_store(smc, ga, ga + 5120, off,     relu_add4(p0, q0));
            split_store(smc, ga, ga + 5120, off + 8, relu_add4(p1, q1));
        }
        bar_half(barid);

        float ac2[2][4][4];
        #pragma unroll
        for (int m = 0; m < 2; ++m)
            #pragma unroll
            for (int n = 0; n < 4; ++n)
                #pragma unroll
                for (int q = 0; q < 4; ++q) ac2[m][n][q] = 0.f;

        #pragma unroll
        for (int c = 0; c < 8; ++c) {
            // issue next chunk's gathers (latency hidden by MMA below)
            float4 p0, p1, q0, q1;
            if (c < 7) {
                p0 = pq4[prow + (c + 1) * 8];
                p1 = pq4[prow + (c + 1) * 8 + 1];
                q0 = pq4[qrow + (c + 1) * 8];
                q1 = pq4[qrow + (c + 1) * 8 + 1];
            }
            const uint32_t abase = sb + (uint32_t)(ga + (c & 1) * 10240);
            const uint32_t bbase = sb + E_B + (uint32_t)(c * 10240);
            #pragma unroll
            for (int ks = 0; ks < 2; ++ks) {
                uint32_t ah[2][4], al[2][4];
                #pragma unroll
                for (int mt = 0; mt < 2; ++mt) {
                    uint32_t aaddr = abase +
                        (uint32_t)((wr * 32 + mt * 16 + lrow) * 80 + (ks * 16 + lcol) * 2);
                    ldsm_x4(ah[mt][0], ah[mt][1], ah[mt][2], ah[mt][3], aaddr);
                    ldsm_x4(al[mt][0], al[mt][1], al[mt][2], al[mt][3], aaddr + 5120);
                }
                #pragma unroll
                for (int np = 0; np < 2; ++np) {
                    uint32_t baddr = bbase +
                        (uint32_t)((wc * 32 + np * 16 + lrow) * 80 + (ks * 16 + lcol) * 2);
                    uint32_t bh0, bh1, bh2, bh3, bl0, bl1, bl2, bl3;
                    ldsm_x4(bh0, bh1, bh2, bh3, baddr);
                    ldsm_x4(bl0, bl1, bl2, bl3, baddr + 81920);
                    const int nb = np * 2;
                    #pragma unroll
                    for (int mt = 0; mt < 2; ++mt) {
                        mma_bf16(ac2[mt][nb],     ah[mt], bh0, bh2);
                        mma_bf16(ac2[mt][nb + 1], ah[mt], bh1, bh3);
                        mma_bf16(ac2[mt][nb],     al[mt], bh0, bh2);
                        mma_bf16(ac2[mt][nb + 1], al[mt], bh1, bh3);
                        mma_bf16(ac2[mt][nb],     ah[mt], bl0, bl2);
                        mma_bf16(ac2[mt][nb + 1], ah[mt], bl1, bl3);
                    }
                }
            }
            // convert + store next chunk into the other buffer
            if (c < 7) {
                const int ab = ga + ((c + 1) & 1) * 10240;
                int off = r * 80 + sg * 16;
                split_store(smc, ab, ab + 5120, off,     relu_add4(p0, q0));
                split_store(smc, ab, ab + 5120, off + 8, relu_add4(p1, q1));
            }
            bar_half(barid);
        }

        // ---- epilogue: bias+relu, vectorized red scatter ----
        const int* stor =
            reinterpret_cast<const int*>(smc + E_TO + (g * 2 + (tcnt & 1)) * 256);
        #pragma unroll
        for (int mt = 0; mt < 2; ++mt)
            #pragma unroll
            for (int nt = 0; nt < 4; ++nt) {
                int cc = wc * 32 + nt * 8 + 2 * (lane & 3);
                int r0 = wr * 32 + mt * 16 + (lane >> 2);   // local row
                int r1 = r0 + 8;
                float* d = ac2[mt][nt];
                float v0 = fmaxf(d[0] + bv0[nt], 0.f), v1 = fmaxf(d[1] + bv1[nt], 0.f);
                float v2 = fmaxf(d[2] + bv0[nt], 0.f), v3 = fmaxf(d[3] + bv1[nt], 0.f);
                if (g * 64 + r0 < rem)
                    red_add2(g_agg + (size_t)stor[r0] * DD + cc, v0, v1);
                if (g * 64 + r1 < rem)
                    red_add2(g_agg + (size_t)stor[r1] * DD + cc, v2, v3);
            }
    }
}

// ============================ node kernel ===================================
#define SM_B0   0
#define SM_B1   1024
#define SM_AHI  4096
#define SM_ALO  (4096 + 67584)          // 71680
#define SM_B    (71680 + 67584)         // 139264
#define N_BHALF 20480
#define N_BBUF  40960
#define N_SMEM  (139264 + 2 * N_BBUF)   // 221184
#define AROW 528

__global__ void __launch_bounds__(512, 1) node_kernel(
    const float* __restrict__ feat,
    const float* __restrict__ b0, const float* __restrict__ b1,
    float* __restrict__ outp)
{
    extern __shared__ char smc[];
    const uint32_t sb = smem_u32(smc);
    const int tid  = threadIdx.x;
    const int wid  = tid >> 5;
    const int lane = tid & 31;
    const int wr   = wid & 3;
    const int wc   = wid >> 2;
    const int lrow = ((lane >> 3) & 1) * 8 + (lane & 7);
    const int lcol = (lane >> 4) * 8;

    float* b0s = reinterpret_cast<float*>(smc + SM_B0);
    float* b1s = reinterpret_cast<float*>(smc + SM_B1);

    const int tile0 = blockIdx.x * TM;

    if (tid < 256) b0s[tid] = b0[tid];
    if (tid >= 256 && tid < 384) b1s[tid - 256] = b1[tid - 256];

    stage_b(sb + SM_B, tid, g_uW0h, g_uW0l, 0, 0, 256, HH, N_BHALF);
    CP_COMMIT();
    __syncthreads();

    {
        const float4* f4 = reinterpret_cast<const float4*>(feat);
        const float4* a4 = reinterpret_cast<const float4*>(g_agg);
        #pragma unroll
        for (int it = 0; it < 16; ++it) {
            int ci = tid + it * 512;
            int r  = ci >> 6;
            int c4 = ci & 63;
            int node = tile0 + r;
            float4 v = make_float4(0.f, 0.f, 0.f, 0.f);
            if (node < NN)
                v = (c4 < 32) ? a4[(size_t)node * 32 + c4]
                              : f4[(size_t)node * 32 + (c4 - 32)];
            split_store(smc, SM_AHI, SM_ALO, r * AROW + c4 * 8, v);
        }
    }
    __syncthreads();

    float acc[2][8][4];
    #pragma unroll
    for (int m = 0; m < 2; ++m)
        #pragma unroll
        for (int n = 0; n < 8; ++n)
            #pragma unroll
            for (int q = 0; q < 4; ++q) acc[m][n][q] = 0.f;

    for (int c = 0; c < 8; ++c) {
        if (c < 7)
            stage_b(sb + SM_B + (uint32_t)((c + 1) & 1) * N_BBUF, tid,
                    g_uW0h, g_uW0l, 0, c + 1, 256, HH, N_BHALF);
        CP_COMMIT();
        CP_WAIT(1);
        __syncthreads();
        const uint32_t bbase = sb + SM_B + (uint32_t)(c & 1) * N_BBUF;
        #pragma unroll
        for (int ks = 0; ks < 2; ++ks) {
            const int kA = c * 32 + ks * 16;
            uint32_t ah[2][4], al[2][4];
            #pragma unroll
            for (int mt = 0; mt < 2; ++mt) {
                uint32_t aaddr = sb + SM_AHI +
                    (uint32_t)((wr * 32 + mt * 16 + lrow) * AROW + (kA + lcol) * 2);
                ldsm_x4(ah[mt][0], ah[mt][1], ah[mt][2], ah[mt][3], aaddr);
                ldsm_x4(al[mt][0], al[mt][1], al[mt][2], al[mt][3],
                        aaddr + (SM_ALO - SM_AHI));
            }
            #pragma unroll
            for (int np = 0; np < 4; ++np) {
                uint32_t baddr = bbase +
                    (uint32_t)((wc * 64 + np * 16 + lrow) * 80 + (ks * 16 + lcol) * 2);
                uint32_t bh0, bh1, bh2, bh3, bl0, bl1, bl2, bl3;
                ldsm_x4(bh0, bh1, bh2, bh3, baddr);
                ldsm_x4(bl0, bl1, bl2, bl3, baddr + N_BHALF);
                const int nb = np * 2;
                #pragma unroll
                for (int mt = 0; mt < 2; ++mt) {
                    mma_bf16(acc[mt][nb],     ah[mt], bh0, bh2);
                    mma_bf16(acc[mt][nb + 1], ah[mt], bh1, bh3);
                    mma_bf16(acc[mt][nb],     al[mt], bh0, bh2);
                    mma_bf16(acc[mt][nb + 1], al[mt], bh1, bh3);
                    mma_bf16(acc[mt][nb],     ah[mt], bl0, bl2);
                    mma_bf16(acc[mt][nb + 1], ah[mt], bl1, bl3);
                }
            }
        }
        __syncthreads();
    }

    stage_b(sb + SM_B, tid, g_uW1h, g_uW1l, 0, 0, 128, HH, N_BHALF);
    CP_COMMIT();

    #pragma unroll
    for (int mt = 0; mt < 2; ++mt)
        #pragma unroll
        for (int nt = 0; nt < 8; ++nt) {
            int cc = wc * 64 + nt * 8 + 2 * (lane & 3);
            int r0 = wr * 32 + mt * 16 + (lane >> 2);
            float* d = acc[mt][nt];
            float v0 = fmaxf(d[0] + b0s[cc], 0.f), v1 = fmaxf(d[1] + b0s[cc + 1], 0.f);
            float v2 = fmaxf(d[2] + b0s[cc], 0.f), v3 = fmaxf(d[3] + b0s[cc + 1], 0.f);
            __nv_bfloat16 h0 = __float2bfloat16(v0), h1 = __float2bfloat16(v1);
            __nv_bfloat16 h2 = __float2bfloat16(v2), h3 = __float2bfloat16(v3);
            int o0 = r0 * AROW + cc * 2;
            int o1 = (r0 + 8) * AROW + cc * 2;
            *reinterpret_cast<uint32_t*>(smc + SM_AHI + o0) = pack_bf16(v0, v1);
            *reinterpret_cast<uint32_t*>(smc + SM_AHI + o1) = pack_bf16(v2, v3);
            *reinterpret_cast<uint32_t*>(smc + SM_ALO + o0) =
                pack_bf16(v0 - __bfloat162float(h0), v1 - __bfloat162float(h1));
            *reinterpret_cast<uint32_t*>(smc + SM_ALO + o1) =
                pack_bf16(v2 - __bfloat162float(h2), v3 - __bfloat162float(h3));
        }

    float ac2[2][4][4];
    #pragma unroll
    for (int m = 0; m < 2; ++m)
        #pragma unroll
        for (int n = 0; n < 4; ++n)
            #pragma unroll
            for (int q = 0; q < 4; ++q) ac2[m][n][q] = 0.f;

    for (int c = 0; c < 8; ++c) {
        if (c < 7)
            stage_b(sb + SM_B + (uint32_t)((c + 1) & 1) * N_BBUF, tid,
                    g_uW1h, g_uW1l, 0, c + 1, 128, HH, N_BHALF);
        CP_COMMIT();
        CP_WAIT(1);
        __syncthreads();
        const uint32_t bbase = sb + SM_B + (uint32_t)(c & 1) * N_BBUF;
        #pragma unroll
        for (int ks = 0; ks < 2; ++ks) {
            const int kA = c * 32 + ks * 16;
            uint32_t ah[2][4], al[2][4];
            #pragma unroll
            for (int mt = 0; mt < 2; ++mt) {
                uint32_t aaddr = sb + SM_AHI +
                    (uint32_t)((wr * 32 + mt * 16 + lrow) * AROW + (kA + lcol) * 2);
                ldsm_x4(ah[mt][0], ah[mt][1], ah[mt][2], ah[mt][3], aaddr);
                ldsm_x4(al[mt][0], al[mt][1], al[mt][2], al[mt][3],
                        aaddr + (SM_ALO - SM_AHI));
            }
            #pragma unroll
            for (int np = 0; np < 2; ++np) {
                uint32_t baddr = bbase +
                    (uint32_t)((wc * 32 + np * 16 + lrow) * 80 + (ks * 16 + lcol) * 2);
                uint32_t bh0, bh1, bh2, bh3, bl0, bl1, bl2, bl3;
                ldsm_x4(bh0, bh1, bh2, bh3, baddr);
                ldsm_x4(bl0, bl1, bl2, bl3, baddr + N_BHALF);
                const int nb = np * 2;
                #pragma unroll
                for (int mt = 0; mt < 2; ++mt) {
                    mma_bf16(ac2[mt][nb],     ah[mt], bh0, bh2);
                    mma_bf16(ac2[mt][nb + 1], ah[mt], bh1, bh3);
                    mma_bf16(ac2[mt][nb],     al[mt], bh0, bh2);
                    mma_bf16(ac2[mt][nb + 1], al[mt], bh1, bh3);
                    mma_bf16(ac2[mt][nb],     ah[mt], bl0, bl2);
                    mma_bf16(ac2[mt][nb + 1], ah[mt], bl1, bl3);
                }
            }
        }
        __syncthreads();
    }

    #pragma unroll
    for (int mt = 0; mt < 2; ++mt)
        #pragma unroll
        for (int nt = 0; nt < 4; ++nt) {
            int cc = wc * 32 + nt * 8 + 2 * (lane & 3);
            int r0 = wr * 32 + mt * 16 + (lane >> 2);
            int r1 = r0 + 8;
            float* d = ac2[mt][nt];
            float v0 = fmaxf(d[0] + b1s[cc], 0.f), v1 = fmaxf(d[1] + b1s[cc + 1], 0.f);
            float v2 = fmaxf(d[2] + b1s[cc], 0.f), v3 = fmaxf(d[3] + b1s[cc + 1], 0.f);
            int n0 = tile0 + r0, n1 = tile0 + r1;
            if (n0 < NN) {
                float2 f = *reinterpret_cast<const float2*>(feat + (size_t)n0 * DD + cc);
                *reinterpret_cast<float2*>(outp + (size_t)n0 * DD + cc) =
                    make_float2(f.x + v0, f.y + v1);
            }
            if (n1 < NN) {
                float2 f = *reinterpret_cast<const float2*>(feat + (size_t)n1 * DD + cc);
                *reinterpret_cast<float2*>(outp + (size_t)n1 * DD + cc) =
                    make_float2(f.x + v2, f.y + v3);
            }
        }
}

// ============================== host launch =================================
extern "C" void kernel_launch(void* const* d_in, const int* in_sizes, int n_in,
                              void* d_out, int out_size)
{
    const float* feat  = (const float*)d_in[0];
    const int*   f_idx = (const int*)  d_in[1];
    const int*   t_idx = (const int*)  d_in[2];
    const float* msgW0 = (const float*)d_in[3];
    const float* msgb0 = (const float*)d_in[4];
    const float* msgW1 = (const float*)d_in[5];
    const float* msgb1 = (const float*)d_in[6];
    const float* updW0 = (const float*)d_in[7];
    const float* updb0 = (const float*)d_in[8];
    const float* updW1 = (const float*)d_in[9];
    const float* updb1 = (const float*)d_in[10];
    float* out = (float*)d_out;

    cudaFuncSetAttribute(pq_kernel,   cudaFuncAttributeMaxDynamicSharedMemorySize, P_SMEM);
    cudaFuncSetAttribute(edge_kernel, cudaFuncAttributeMaxDynamicSharedMemorySize, E_SMEM);
    cudaFuncSetAttribute(node_kernel, cudaFuncAttributeMaxDynamicSharedMemorySize, N_SMEM);

    conv_w_kernel<<<768, 256>>>(msgW0, updW0, msgW1, updW1);
    zero_agg_kernel<<<1024, 256>>>();

    const int pq_tiles   = (NN + TM - 1) / TM;  // 391
    const int node_tiles = (NN + TM - 1) / TM;  // 391

    pq_kernel<<<pq_tiles, 512, P_SMEM>>>(feat, msgb0);
    edge_kernel<<<152, 512, E_SMEM>>>(f_idx, t_idx, msgb1);
    node_kernel<<<node_tiles, 512, N_SMEM>>>(feat, updb0, updb1, out);
}

// round 12
// speedup vs baseline: 1.7638x; 1.0347x over previous
#include <cuda_runtime.h>
#include <cuda_bf16.h>
#include <cstdint>
#include <cstddef>

#define NN 50000
#define NE 600000
#define DD 128
#define HH 256
#define TM 128

// ============================ device scratch ================================
__device__ float g_agg[(size_t)NN * DD];
__device__ float g_PQ[(size_t)NN * 512];   // per-node [P|Q] for msg MLP
__device__ float g_R[(size_t)NN * HH];     // per-node R = feat@uW0b + updb0
// weights transposed to [N][K] row-major, bf16 hi/lo split
__device__ __nv_bfloat16 g_c0h[512 * DD], g_c0l[512 * DD];   // msg [W0a|W0b]^T : [512][128]
__device__ __nv_bfloat16 g_uah[HH * DD],  g_ual[HH * DD];    // upd W0a^T: [256][128]
__device__ __nv_bfloat16 g_ubh[HH * DD],  g_ubl[HH * DD];    // upd W0b^T: [256][128]
__device__ __nv_bfloat16 g_mW1h[DD * HH], g_mW1l[DD * HH];   // msg W1^T: [128][256]
__device__ __nv_bfloat16 g_uW1h[DD * HH], g_uW1l[DD * HH];   // upd W1^T: [128][256]

// ============================ PTX helpers ===================================
__device__ __forceinline__ uint32_t smem_u32(const void* p) {
    uint32_t a;
    asm("{ .reg .u64 t; cvta.to.shared.u64 t, %1; cvt.u32.u64 %0, t; }" : "=r"(a) : "l"(p));
    return a;
}
__device__ __forceinline__ void ldsm_x4(uint32_t& r0, uint32_t& r1, uint32_t& r2,
                                        uint32_t& r3, uint32_t addr) {
    asm volatile("ldmatrix.sync.aligned.m8n8.x4.shared.b16 {%0,%1,%2,%3}, [%4];"
                 : "=r"(r0), "=r"(r1), "=r"(r2), "=r"(r3) : "r"(addr));
}
__device__ __forceinline__ void mma_bf16(float* d, const uint32_t* a,
                                         uint32_t b0, uint32_t b1) {
    asm volatile(
        "mma.sync.aligned.m16n8k16.row.col.f32.bf16.bf16.f32 "
        "{%0,%1,%2,%3},{%4,%5,%6,%7},{%8,%9},{%0,%1,%2,%3};"
        : "+f"(d[0]), "+f"(d[1]), "+f"(d[2]), "+f"(d[3])
        : "r"(a[0]), "r"(a[1]), "r"(a[2]), "r"(a[3]), "r"(b0), "r"(b1));
}
__device__ __forceinline__ uint32_t pack_bf16(float a, float b) {
    __nv_bfloat162 t = __floats2bfloat162_rn(a, b);
    return *reinterpret_cast<uint32_t*>(&t);
}
__device__ __forceinline__ void cpa16(uint32_t dst, const void* src) {
    asm volatile("cp.async.cg.shared.global [%0], [%1], 16;"
                 :: "r"(dst), "l"(src) : "memory");
}
#define CP_COMMIT() asm volatile("cp.async.commit_group;" ::: "memory")
#define CP_WAIT(n)  asm volatile("cp.async.wait_group %0;" :: "n"(n) : "memory")
__device__ __forceinline__ void red_add2(float* a, float v0, float v1) {
    asm volatile("red.global.add.v2.f32 [%0], {%1, %2};"
                 :: "l"(a), "f"(v0), "f"(v1) : "memory");
}
__device__ __forceinline__ void bar_q(int id) {
    asm volatile("bar.sync %0, 128;" :: "r"(id) : "memory");
}

// store float4 -> hi/lo bf16x2 pairs at byte offset off in two tiles
__device__ __forceinline__ void split_store(char* smc, int hi_base, int lo_base,
                                            int off, float4 v) {
    __nv_bfloat16 h0 = __float2bfloat16(v.x), h1 = __float2bfloat16(v.y);
    __nv_bfloat16 h2 = __float2bfloat16(v.z), h3 = __float2bfloat16(v.w);
    uint2 H, L;
    H.x = pack_bf16(v.x, v.y);
    H.y = pack_bf16(v.z, v.w);
    L.x = pack_bf16(v.x - __bfloat162float(h0), v.y - __bfloat162float(h1));
    L.y = pack_bf16(v.z - __bfloat162float(h2), v.w - __bfloat162float(h3));
    *reinterpret_cast<uint2*>(smc + hi_base + off) = H;
    *reinterpret_cast<uint2*>(smc + lo_base + off) = L;
}

__device__ __forceinline__ float4 relu_add4(float4 p, float4 q) {
    float4 v;
    v.x = fmaxf(p.x + q.x, 0.f);
    v.y = fmaxf(p.y + q.y, 0.f);
    v.z = fmaxf(p.z + q.z, 0.f);
    v.w = fmaxf(p.w + q.w, 0.f);
    return v;
}

// =========================== prelude kernels ================================
__global__ void zero_agg_kernel() {
    const size_t n4 = (size_t)NN * DD / 4;
    float4 z = make_float4(0.f, 0.f, 0.f, 0.f);
    for (size_t i = (size_t)blockIdx.x * blockDim.x + threadIdx.x; i < n4;
         i += (size_t)gridDim.x * blockDim.x)
        reinterpret_cast<float4*>(g_agg)[i] = z;
}

__device__ __forceinline__ void put_split(__nv_bfloat16* h, __nv_bfloat16* l,
                                          int idx, float w) {
    __nv_bfloat16 hi = __float2bfloat16(w);
    h[idx] = hi;
    l[idx] = __float2bfloat16(w - __bfloat162float(hi));
}

__global__ void conv_w_kernel(const float* __restrict__ mW0, const float* __restrict__ uW0,
                              const float* __restrict__ mW1, const float* __restrict__ uW1) {
    int i = blockIdx.x * blockDim.x + threadIdx.x;
    if (i >= 196608) return;
    if (i < 65536) {                      // msg [W0a|W0b]^T
        int n = i >> 7, k = i & 127;
        float w = (n < 256) ? mW0[k * HH + n] : mW0[(128 + k) * HH + (n - 256)];
        put_split(g_c0h, g_c0l, n * DD + k, w);
    } else if (i < 98304) {               // upd W0a^T (agg part)
        int j = i - 65536, n = j >> 7, k = j & 127;
        put_split(g_uah, g_ual, n * DD + k, uW0[k * HH + n]);
    } else if (i < 131072) {              // upd W0b^T (feat part)
        int j = i - 98304, n = j >> 7, k = j & 127;
        put_split(g_ubh, g_ubl, n * DD + k, uW0[(DD + k) * HH + n]);
    } else if (i < 163840) {              // msg W1^T
        int j = i - 131072, k = j >> 7, n = j & 127;
        put_split(g_mW1h, g_mW1l, n * HH + k, mW1[j]);
    } else {                              // upd W1^T
        int j = i - 163840, k = j >> 7, n = j & 127;
        put_split(g_uW1h, g_uW1l, n * HH + k, uW1[j]);
    }
}

// generic B-chunk stager: nrows x 32 K-cols, BROW=80, 512 threads
__device__ __forceinline__ void stage_b(uint32_t bbase, int tid,
                                        const __nv_bfloat16* Wh,
                                        const __nv_bfloat16* Wl,
                                        int row_base, int chunk, int nrows,
                                        int kstride, int bhalf) {
    #pragma unroll
    for (int i = 0; i < 2; ++i) {
        int idx = tid + i * 512;
        if (idx < nrows * 4) {
            int row = idx >> 2, seg = idx & 3;
            uint32_t d = bbase + (uint32_t)(row * 80 + seg * 16);
            const int so = (row_base + row) * kstride + chunk * 32 + seg * 8;
            cpa16(d, Wh + so);
            cpa16(d + bhalf, Wl + so);
        }
    }
}

// ======================= PQ+R precompute kernel =============================
// h=0: P = feat@msgW0a + msgb0 -> g_PQ[:,0:256]
// h=1: Q = feat@msgW0b         -> g_PQ[:,256:512]
// h=2: R = feat@updW0b + updb0 -> g_R
#define P_B0    0
#define P_UB0   1024
#define P_AHI   4096
#define P_ALO   (4096 + 34816)          // 38912
#define P_B     (38912 + 34816)         // 73728
#define P_BHALF 20480
#define P_BBUF  40960
#define P_SMEM  (73728 + 2 * P_BBUF)    // 155648
#define AROW2   272

__global__ void __launch_bounds__(512, 1) pq_kernel(const float* __restrict__ feat,
                                                    const float* __restrict__ b0,
                                                    const float* __restrict__ ub0) {
    extern __shared__ char smc[];
    const uint32_t sb = smem_u32(smc);
    const int tid  = threadIdx.x;
    const int wid  = tid >> 5;
    const int lane = tid & 31;
    const int wr   = wid & 3;
    const int wc   = wid >> 2;
    const int lrow = ((lane >> 3) & 1) * 8 + (lane & 7);
    const int lcol = (lane >> 4) * 8;
    float* b0s  = reinterpret_cast<float*>(smc + P_B0);
    float* ub0s = reinterpret_cast<float*>(smc + P_UB0);

    const int tile0 = blockIdx.x * TM;
    if (tid < 256) b0s[tid] = b0[tid];
    else ub0s[tid - 256] = ub0[tid - 256];

    stage_b(sb + P_B, tid, g_c0h, g_c0l, 0, 0, 256, DD, P_BHALF);
    CP_COMMIT();

    {
        const float4* f4 = reinterpret_cast<const float4*>(feat);
        #pragma unroll
        for (int it = 0; it < 8; ++it) {
            int ci = tid + it * 512;
            int r  = ci >> 5;
            int c4 = ci & 31;
            int node = tile0 + r;
            float4 v = make_float4(0.f, 0.f, 0.f, 0.f);
            if (node < NN) v = f4[(size_t)node * 32 + c4];
            split_store(smc, P_AHI, P_ALO, r * AROW2 + c4 * 8, v);
        }
    }
    __syncthreads();

    for (int h = 0; h < 3; ++h) {
        float acc[2][8][4];
        #pragma unroll
        for (int m = 0; m < 2; ++m)
            #pragma unroll
            for (int n = 0; n < 8; ++n)
                #pragma unroll
                for (int q = 0; q < 4; ++q) acc[m][n][q] = 0.f;

        for (int c = 0; c < 4; ++c) {
            int gg = h * 4 + c;
            if (gg < 11) {
                int gn = gg + 1, hn = gn >> 2, cn = gn & 3;
                const __nv_bfloat16* Wh = (hn < 2) ? g_c0h : g_ubh;
                const __nv_bfloat16* Wl = (hn < 2) ? g_c0l : g_ubl;
                int rb = (hn == 1) ? 256 : 0;
                stage_b(sb + P_B + (uint32_t)(gn & 1) * P_BBUF, tid,
                        Wh, Wl, rb, cn, 256, DD, P_BHALF);
            }
            CP_COMMIT();
            CP_WAIT(1);
            __syncthreads();
            const uint32_t bbase = sb + P_B + (uint32_t)(gg & 1) * P_BBUF;
            #pragma unroll
            for (int ks = 0; ks < 2; ++ks) {
                const int kA = c * 32 + ks * 16;
                uint32_t ah[2][4], al[2][4];
                #pragma unroll
                for (int mt = 0; mt < 2; ++mt) {
                    uint32_t aaddr = sb + P_AHI +
                        (uint32_t)((wr * 32 + mt * 16 + lrow) * AROW2 + (kA + lcol) * 2);
                    ldsm_x4(ah[mt][0], ah[mt][1], ah[mt][2], ah[mt][3], aaddr);
                    ldsm_x4(al[mt][0], al[mt][1], al[mt][2], al[mt][3],
                            aaddr + (P_ALO - P_AHI));
                }
                #pragma unroll
                for (int np = 0; np < 4; ++np) {
                    uint32_t baddr = bbase +
                        (uint32_t)((wc * 64 + np * 16 + lrow) * 80 + (ks * 16 + lcol) * 2);
                    uint32_t bh0, bh1, bh2, bh3, bl0, bl1, bl2, bl3;
                    ldsm_x4(bh0, bh1, bh2, bh3, baddr);
                    ldsm_x4(bl0, bl1, bl2, bl3, baddr + P_BHALF);
                    const int nb = np * 2;
                    #pragma unroll
                    for (int mt = 0; mt < 2; ++mt) {
                        mma_bf16(acc[mt][nb],     ah[mt], bh0, bh2);
                        mma_bf16(acc[mt][nb + 1], ah[mt], bh1, bh3);
                        mma_bf16(acc[mt][nb],     al[mt], bh0, bh2);
                        mma_bf16(acc[mt][nb + 1], al[mt], bh1, bh3);
                        mma_bf16(acc[mt][nb],     ah[mt], bl0, bl2);
                        mma_bf16(acc[mt][nb + 1], ah[mt], bl1, bl3);
                    }
                }
            }
            __syncthreads();
        }

        #pragma unroll
        for (int mt = 0; mt < 2; ++mt)
            #pragma unroll
            for (int nt = 0; nt < 8; ++nt) {
                int cc = wc * 64 + nt * 8 + 2 * (lane & 3);
                int r0 = wr * 32 + mt * 16 + (lane >> 2);
                int r1 = r0 + 8;
                float* d = acc[mt][nt];
                float bb0 = (h == 0) ? b0s[cc]      : (h == 2) ? ub0s[cc]     : 0.f;
                float bb1 = (h == 0) ? b0s[cc + 1]  : (h == 2) ? ub0s[cc + 1] : 0.f;
                int n0 = tile0 + r0, n1 = tile0 + r1;
                if (h < 2) {
                    int co = h * 256 + cc;
                    if (n0 < NN)
                        *reinterpret_cast<float2*>(g_PQ + (size_t)n0 * 512 + co) =
                            make_float2(d[0] + bb0, d[1] + bb1);
                    if (n1 < NN)
                        *reinterpret_cast<float2*>(g_PQ + (size_t)n1 * 512 + co) =
                            make_float2(d[2] + bb0, d[3] + bb1);
                } else {
                    if (n0 < NN)
                        *reinterpret_cast<float2*>(g_R + (size_t)n0 * HH + cc) =
                            make_float2(d[0] + bb0, d[1] + bb1);
                    if (n1 < NN)
                        *reinterpret_cast<float2*>(g_R + (size_t)n1 * HH + cc) =
                            make_float2(d[2] + bb0, d[3] + bb1);
                }
            }
    }
}

// ============== edge kernel (persistent, FOUR independent groups) ===========
// Group g (warps 4g..4g+3, 128 thr) processes its own stream of 32-row edge
// tiles: own A double-buffers, own sto parity buffers, own named barrier.
// Each group has exactly one warp per SMSP -> 4 independently-phased streams
// per scheduler. W1 smem-resident.
#define TME    32                      // edge rows per group-tile
#define E_B1   0                       // 128 floats
#define E_TO   512                     // 8 x 32 ints: [g][parity]
#define E_A    4096                    // per group: 2 bufs of (hi 2560 + lo 2560)
#define E_B    (4096 + 40960)          // 45056; B hi: 8 chunks * 10240; lo at +81920
#define E_SMEM (45056 + 163840)        // 208896

#define EDGE_T32 (NE / TME)            // 18750

__global__ void __launch_bounds__(512, 1) edge_kernel(
    const int* __restrict__ from_idx, const int* __restrict__ to_idx,
    const float* __restrict__ b1)
{
    extern __shared__ char smc[];
    const uint32_t sb = smem_u32(smc);
    const int tid  = threadIdx.x;
    const int wid  = tid >> 5;
    const int lane = tid & 31;
    const int g    = wid >> 2;            // group 0..3
    const int wc   = wid & 3;             // col group 0..3 (32 cols each)
    const int lrow = ((lane >> 3) & 1) * 8 + (lane & 7);
    const int lcol = (lane >> 4) * 8;
    const int barid = 1 + g;

    float* b1s = reinterpret_cast<float*>(smc + E_B1);
    if (tid < 128) b1s[tid] = b1[tid];

    // ---- stage resident W1 hi/lo once ----
    #pragma unroll
    for (int i = 0; i < 8; ++i) {
        int idx = tid + i * 512;          // c*512 + row*4 + seg
        int c = idx >> 9, rs = idx & 511;
        int row = rs >> 2, seg = rs & 3;
        uint32_t d = sb + E_B + (uint32_t)(c * 10240 + row * 80 + seg * 16);
        int so = row * HH + c * 32 + seg * 8;
        cpa16(d, g_mW1h + so);
        cpa16(d + 81920, g_mW1l + so);
    }
    CP_COMMIT();
    CP_WAIT(0);
    __syncthreads();                      // last full-CTA sync

    // hoist bias values into registers (constant across tiles)
    float bv0[4], bv1[4];
    #pragma unroll
    for (int nt = 0; nt < 4; ++nt) {
        int cc = wc * 32 + nt * 8 + 2 * (lane & 3);
        bv0[nt] = b1s[cc];
        bv1[nt] = b1s[cc + 1];
    }

    const float4* pq4 = reinterpret_cast<const float4*>(g_PQ);
    const int ptid = tid & 127;           // group-local thread id
    const int r  = ptid >> 2;             // local row 0..31
    const int sg = ptid & 3;              // seg: 2 float4 per seg
    const int ga = E_A + g * 10240;       // group A buffers

    int tcnt = 0;
    for (int tile = blockIdx.x * 4 + g; tile < EDGE_T32; tile += gridDim.x * 4, ++tcnt) {
        const int tile0 = tile * TME;

        int fr = from_idx[tile0 + r];
        int to = to_idx[tile0 + r];
        int* stob = reinterpret_cast<int*>(smc + E_TO + (g * 2 + (tcnt & 1)) * 128);
        if (sg == 0) stob[r] = to;

        const size_t prow = (size_t)fr * 128 + sg * 2;        // float4 units
        const size_t qrow = (size_t)to * 128 + 64 + sg * 2;

        // produce chunk 0 into buf 0
        {
            float4 p0 = pq4[prow], p1 = pq4[prow + 1];
            float4 q0 = pq4[qrow], q1 = pq4[qrow + 1];
            int off = r * 80 + sg * 16;
            split_store(smc, ga, ga + 2560, off,     relu_add4(p0, q0));
            split_store(smc, ga, ga + 2560, off + 8, relu_add4(p1, q1));
        }
        bar_q(barid);

        float ac2[2][4][4];
        #pragma unroll
        for (int m = 0; m < 2; ++m)
            #pragma unroll
            for (int n = 0; n < 4; ++n)
                #pragma unroll
                for (int q = 0; q < 4; ++q) ac2[m][n][q] = 0.f;

        #pragma unroll
        for (int c = 0; c < 8; ++c) {
            // issue next chunk's gathers (latency hidden by MMA below)
            float4 p0, p1, q0, q1;
            if (c < 7) {
                p0 = pq4[prow + (c + 1) * 8];
                p1 = pq4[prow + (c + 1) * 8 + 1];
                q0 = pq4[qrow + (c + 1) * 8];
                q1 = pq4[qrow + (c + 1) * 8 + 1];
            }
            const uint32_t abase = sb + (uint32_t)(ga + (c & 1) * 5120);
            const uint32_t bbase = sb + E_B + (uint32_t)(c * 10240);
            #pragma unroll
            for (int ks = 0; ks < 2; ++ks) {
                uint32_t ah[2][4], al[2][4];
                #pragma unroll
                for (int mt = 0; mt < 2; ++mt) {
                    uint32_t aaddr = abase +
                        (uint32_t)((mt * 16 + lrow) * 80 + (ks * 16 + lcol) * 2);
                    ldsm_x4(ah[mt][0], ah[mt][1], ah[mt][2], ah[mt][3], aaddr);
                    ldsm_x4(al[mt][0], al[mt][1], al[mt][2], al[mt][3], aaddr + 2560);
                }
                #pragma unroll
                for (int np = 0; np < 2; ++np) {
                    uint32_t baddr = bbase +
                        (uint32_t)((wc * 32 + np * 16 + lrow) * 80 + (ks * 16 + lcol) * 2);
                    uint32_t bh0, bh1, bh2, bh3, bl0, bl1, bl2, bl3;
                    ldsm_x4(bh0, bh1, bh2, bh3, baddr);
                    ldsm_x4(bl0, bl1, bl2, bl3, baddr + 81920);
                    const int nb = np * 2;
                    #pragma unroll
                    for (int mt = 0; mt < 2; ++mt) {
                        mma_bf16(ac2[mt][nb],     ah[mt], bh0, bh2);
                        mma_bf16(ac2[mt][nb + 1], ah[mt], bh1, bh3);
                        mma_bf16(ac2[mt][nb],     al[mt], bh0, bh2);
                        mma_bf16(ac2[mt][nb + 1], al[mt], bh1, bh3);
                        mma_bf16(ac2[mt][nb],     ah[mt], bl0, bl2);
                        mma_bf16(ac2[mt][nb + 1], ah[mt], bl1, bl3);
                    }
                }
            }
            if (c < 7) {
                const int ab = ga + ((c + 1) & 1) * 5120;
                int off = r * 80 + sg * 16;
                split_store(smc, ab, ab + 2560, off,     relu_add4(p0, q0));
                split_store(smc, ab, ab + 2560, off + 8, relu_add4(p1, q1));
            }
            bar_q(barid);
        }

        // ---- epilogue: bias+relu, vectorized red scatter ----
        const int* stor =
            reinterpret_cast<const int*>(smc + E_TO + (g * 2 + (tcnt & 1)) * 128);
        #pragma unroll
        for (int mt = 0; mt < 2; ++mt)
            #pragma unroll
            for (int nt = 0; nt < 4; ++nt) {
                int cc = wc * 32 + nt * 8 + 2 * (lane & 3);
                int r0 = mt * 16 + (lane >> 2);
                int r1 = r0 + 8;
                float* d = ac2[mt][nt];
                float v0 = fmaxf(d[0] + bv0[nt], 0.f), v1 = fmaxf(d[1] + bv1[nt], 0.f);
                float v2 = fmaxf(d[2] + bv0[nt], 0.f), v3 = fmaxf(d[3] + bv1[nt], 0.f);
                red_add2(g_agg + (size_t)stor[r0] * DD + cc, v0, v1);
                red_add2(g_agg + (size_t)stor[r1] * DD + cc, v2, v3);
            }
    }
}

// ============================ node kernel (K-folded) ========================
// S = agg@uW0a (K=128); h = relu(S + R[n]); out = feat + relu(h@uW1 + b1)
#define SM_B1   1024
#define SM_AHI  4096
#define SM_ALO  (4096 + 67584)          // 71680
#define SM_B    (71680 + 67584)         // 139264
#define N_BHALF 20480
#define N_BBUF  40960
#define N_SMEM  (139264 + 2 * N_BBUF)   // 221184
#define AROW 528

__global__ void __launch_bounds__(512, 1) node_kernel(
    const float* __restrict__ feat,
    const float* __restrict__ b1,
    float* __restrict__ outp)
{
    extern __shared__ char smc[];
    const uint32_t sb = smem_u32(smc);
    const int tid  = threadIdx.x;
    const int wid  = tid >> 5;
    const int lane = tid & 31;
    const int wr   = wid & 3;
    const int wc   = wid >> 2;
    const int lrow = ((lane >> 3) & 1) * 8 + (lane & 7);
    const int lcol = (lane >> 4) * 8;

    float* b1s = reinterpret_cast<float*>(smc + SM_B1);

    const int tile0 = blockIdx.x * TM;

    if (tid < 128) b1s[tid] = b1[tid];

    stage_b(sb + SM_B, tid, g_uah, g_ual, 0, 0, 256, DD, N_BHALF);
    CP_COMMIT();
    __syncthreads();

    // gather agg tile [128 x 128]
    {
        const float4* a4 = reinterpret_cast<const float4*>(g_agg);
        #pragma unroll
        for (int it = 0; it < 8; ++it) {
            int ci = tid + it * 512;
            int r  = ci >> 5;
            int c4 = ci & 31;
            int node = tile0 + r;
            float4 v = make_float4(0.f, 0.f, 0.f, 0.f);
            if (node < NN) v = a4[(size_t)node * 32 + c4];
            split_store(smc, SM_AHI, SM_ALO, r * AROW + c4 * 8, v);
        }
    }
    __syncthreads();

    // GEMM1: S = agg@uW0a, K=128 -> 4 chunks
    float acc[2][8][4];
    #pragma unroll
    for (int m = 0; m < 2; ++m)
        #pragma unroll
        for (int n = 0; n < 8; ++n)
            #pragma unroll
            for (int q = 0; q < 4; ++q) acc[m][n][q] = 0.f;

    for (int c = 0; c < 4; ++c) {
        if (c < 3)
            stage_b(sb + SM_B + (uint32_t)((c + 1) & 1) * N_BBUF, tid,
                    g_uah, g_ual, 0, c + 1, 256, DD, N_BHALF);
        CP_COMMIT();
        CP_WAIT(1);
        __syncthreads();
        const uint32_t bbase = sb + SM_B + (uint32_t)(c & 1) * N_BBUF;
        #pragma unroll
        for (int ks = 0; ks < 2; ++ks) {
            const int kA = c * 32 + ks * 16;
            uint32_t ah[2][4], al[2][4];
            #pragma unroll
            for (int mt = 0; mt < 2; ++mt) {
                uint32_t aaddr = sb + SM_AHI +
                    (uint32_t)((wr * 32 + mt * 16 + lrow) * AROW + (kA + lcol) * 2);
                ldsm_x4(ah[mt][0], ah[mt][1], ah[mt][2], ah[mt][3], aaddr);
                ldsm_x4(al[mt][0], al[mt][1], al[mt][2], al[mt][3],
                        aaddr + (SM_ALO - SM_AHI));
            }
            #pragma unroll
            for (int np = 0; np < 4; ++np) {
                uint32_t baddr = bbase +
                    (uint32_t)((wc * 64 + np * 16 + lrow) * 80 + (ks * 16 + lcol) * 2);
                uint32_t bh0, bh1, bh2, bh3, bl0, bl1, bl2, bl3;
                ldsm_x4(bh0, bh1, bh2, bh3, baddr);
                ldsm_x4(bl0, bl1, bl2, bl3, baddr + N_BHALF);
                const int nb = np * 2;
                #pragma unroll
                for (int mt = 0; mt < 2; ++mt) {
                    mma_bf16(acc[mt][nb],     ah[mt], bh0, bh2);
                    mma_bf16(acc[mt][nb + 1], ah[mt], bh1, bh3);
                    mma_bf16(acc[mt][nb],     al[mt], bh0, bh2);
                    mma_bf16(acc[mt][nb + 1], al[mt], bh1, bh3);
                    mma_bf16(acc[mt][nb],     ah[mt], bl0, bl2);
                    mma_bf16(acc[mt][nb + 1], ah[mt], bl1, bl3);
                }
            }
        }
        __syncthreads();
    }

    stage_b(sb + SM_B, tid, g_uW1h, g_uW1l, 0, 0, 128, HH, N_BHALF);
    CP_COMMIT();

    // epilogue1: h = relu(S + R[n]) back into A tiles
    #pragma unroll
    for (int mt = 0; mt < 2; ++mt)
        #pragma unroll
        for (int nt = 0; nt < 8; ++nt) {
            int cc = wc * 64 + nt * 8 + 2 * (lane & 3);
            int r0 = wr * 32 + mt * 16 + (lane >> 2);
            int n0 = tile0 + r0, n1 = n0 + 8;
            float* d = acc[mt][nt];
            float2 R0 = make_float2(0.f, 0.f), R1 = make_float2(0.f, 0.f);
            if (n0 < NN) R0 = *reinterpret_cast<const float2*>(g_R + (size_t)n0 * HH + cc);
            if (n1 < NN) R1 = *reinterpret_cast<const float2*>(g_R + (size_t)n1 * HH + cc);
            float v0 = fmaxf(d[0] + R0.x, 0.f), v1 = fmaxf(d[1] + R0.y, 0.f);
            float v2 = fmaxf(d[2] + R1.x, 0.f), v3 = fmaxf(d[3] + R1.y, 0.f);
            __nv_bfloat16 h0 = __float2bfloat16(v0), h1 = __float2bfloat16(v1);
            __nv_bfloat16 h2 = __float2bfloat16(v2), h3 = __float2bfloat16(v3);
            int o0 = r0 * AROW + cc * 2;
            int o1 = (r0 + 8) * AROW + cc * 2;
            *reinterpret_cast<uint32_t*>(smc + SM_AHI + o0) = pack_bf16(v0, v1);
            *reinterpret_cast<uint32_t*>(smc + SM_AHI + o1) = pack_bf16(v2, v3);
            *reinterpret_cast<uint32_t*>(smc + SM_ALO + o0) =
                pack_bf16(v0 - __bfloat162float(h0), v1 - __bfloat162float(h1));
            *reinterpret_cast<uint32_t*>(smc + SM_ALO + o1) =
                pack_bf16(v2 - __bfloat162float(h2), v3 - __bfloat162float(h3));
        }

    // GEMM2: M = h@uW1, K=256 -> 8 chunks
    float ac2[2][4][4];
    #pragma unroll
    for (int m = 0; m < 2; ++m)
        #pragma unroll
        for (int n = 0; n < 4; ++n)
            #pragma unroll
            for (int q = 0; q < 4; ++q) ac2[m][n][q] = 0.f;

    for (int c = 0; c < 8; ++c) {
        if (c < 7)
            stage_b(sb + SM_B + (uint32_t)((c + 1) & 1) * N_BBUF, tid,
                    g_uW1h, g_uW1l, 0, c + 1, 128, HH, N_BHALF);
        CP_COMMIT();
        CP_WAIT(1);
        __syncthreads();
        const uint32_t bbase = sb + SM_B + (uint32_t)(c & 1) * N_BBUF;
        #pragma unroll
        for (int ks = 0; ks < 2; ++ks) {
            const int kA = c * 32 + ks * 16;
            uint32_t ah[2][4], al[2][4];
            #pragma unroll
            for (int mt = 0; mt < 2; ++mt) {
                uint32_t aaddr = sb + SM_AHI +
                    (uint32_t)((wr * 32 + mt * 16 + lrow) * AROW + (kA + lcol) * 2);
                ldsm_x4(ah[mt][0], ah[mt][1], ah[mt][2], ah[mt][3], aaddr);
                ldsm_x4(al[mt][0], al[mt][1], al[mt][2], al[mt][3],
                        aaddr + (SM_ALO - SM_AHI));
            }
            #pragma unroll
            for (int np = 0; np < 2; ++np) {
                uint32_t baddr = bbase +
                    (uint32_t)((wc * 32 + np * 16 + lrow) * 80 + (ks * 16 + lcol) * 2);
                uint32_t bh0, bh1, bh2, bh3, bl0, bl1, bl2, bl3;
                ldsm_x4(bh0, bh1, bh2, bh3, baddr);
                ldsm_x4(bl0, bl1, bl2, bl3, baddr + N_BHALF);
                const int nb = np * 2;
                #pragma unroll
                for (int mt = 0; mt < 2; ++mt) {
                    mma_bf16(ac2[mt][nb],     ah[mt], bh0, bh2);
                    mma_bf16(ac2[mt][nb + 1], ah[mt], bh1, bh3);
                    mma_bf16(ac2[mt][nb],     al[mt], bh0, bh2);
                    mma_bf16(ac2[mt][nb + 1], al[mt], bh1, bh3);
                    mma_bf16(ac2[mt][nb],     ah[mt], bl0, bl2);
                    mma_bf16(ac2[mt][nb + 1], ah[mt], bl1, bl3);
                }
            }
        }
        __syncthreads();
    }

    // epilogue2: residual store
    #pragma unroll
    for (int mt = 0; mt < 2; ++mt)
        #pragma unroll
        for (int nt = 0; nt < 4; ++nt) {
            int cc = wc * 32 + nt * 8 + 2 * (lane & 3);
            int r0 = wr * 32 + mt * 16 + (lane >> 2);
            int r1 = r0 + 8;
            float* d = ac2[mt][nt];
            float v0 = fmaxf(d[0] + b1s[cc], 0.f), v1 = fmaxf(d[1] + b1s[cc + 1], 0.f);
            float v2 = fmaxf(d[2] + b1s[cc], 0.f), v3 = fmaxf(d[3] + b1s[cc + 1], 0.f);
            int n0 = tile0 + r0, n1 = tile0 + r1;
            if (n0 < NN) {
                float2 f = *reinterpret_cast<const float2*>(feat + (size_t)n0 * DD + cc);
                *reinterpret_cast<float2*>(outp + (size_t)n0 * DD + cc) =
                    make_float2(f.x + v0, f.y + v1);
            }
            if (n1 < NN) {
                float2 f = *reinterpret_cast<const float2*>(feat + (size_t)n1 * DD + cc);
                *reinterpret_cast<float2*>(outp + (size_t)n1 * DD + cc) =
                    make_float2(f.x + v2, f.y + v3);
            }
        }
}

// ============================== host launch =================================
extern "C" void kernel_launch(void* const* d_in, const int* in_sizes, int n_in,
                              void* d_out, int out_size)
{
    const float* feat  = (const float*)d_in[0];
    const int*   f_idx = (const int*)  d_in[1];
    const int*   t_idx = (const int*)  d_in[2];
    const float* msgW0 = (const float*)d_in[3];
    const float* msgb0 = (const float*)d_in[4];
    const float* msgW1 = (const float*)d_in[5];
    const float* msgb1 = (const float*)d_in[6];
    const float* updW0 = (const float*)d_in[7];
    const float* updb0 = (const float*)d_in[8];
    const float* updW1 = (const float*)d_in[9];
    const float* updb1 = (const float*)d_in[10];
    float* out = (float*)d_out;

    cudaFuncSetAttribute(pq_kernel,   cudaFuncAttributeMaxDynamicSharedMemorySize, P_SMEM);
    cudaFuncSetAttribute(edge_kernel, cudaFuncAttributeMaxDynamicSharedMemorySize, E_SMEM);
    cudaFuncSetAttribute(node_kernel, cudaFuncAttributeMaxDynamicSharedMemorySize, N_SMEM);

    conv_w_kernel<<<768, 256>>>(msgW0, updW0, msgW1, updW1);
    zero_agg_kernel<<<1024, 256>>>();

    const int pq_tiles   = (NN + TM - 1) / TM;  // 391
    const int node_tiles = (NN + TM - 1) / TM;  // 391

    pq_kernel<<<pq_tiles, 512, P_SMEM>>>(feat, msgb0, updb0);
    edge_kernel<<<152, 512, E_SMEM>>>(f_idx, t_idx, msgb1);
    node_kernel<<<node_tiles, 512, N_SMEM>>>(feat, updb1, out);
}